// round 13
// baseline (speedup 1.0000x reference)
#include <cuda_runtime.h>
#include <cuda_bf16.h>
#include <math.h>
#include <stdint.h>

#define Bc 2
#define Sc 1024
#define Dc 1024
#define Nc 16
#define Hc 64
#define NHc 1024
#define Rc 2048
#define SCALE 0.125f
#define LOG2E 1.4426950408889634f
#define INFV 1000000.0f
#define EPSV 1e-9f
#define PSTRB 136

typedef __nv_bfloat16 bf;

// ------------------------- scratch -------------------------
__device__ bf g_in16[4 * 2048 * 1024];
__device__ bf g_w16 [5 * 1024 * 1024];
__device__ bf g_proj[4 * 2048 * 1024];
__device__ bf g_av16[2048 * 1024];
__device__ float g_ao[2048 * 1024];
__device__ float g_rwk[32 * 1024];
__device__ float g_rrt[16 * 2048];
__device__ float g_ttd[2048 * 16 * 2];
__device__ unsigned char g_comb[2 * 1024 * 1024];   // ttm | (clsm!=0)<<1

// ------------------------- helpers -------------------------
__device__ __forceinline__ uint32_t cvta_s(const void* p){ return (uint32_t)__cvta_generic_to_shared(p); }
__device__ __forceinline__ void cp16(uint32_t d, const void* s){
    asm volatile("cp.async.cg.shared.global [%0], [%1], 16;" :: "r"(d), "l"(s));
}
__device__ __forceinline__ void ldm_x4(uint32_t* r, uint32_t a){
    asm volatile("ldmatrix.sync.aligned.m8n8.x4.shared.b16 {%0,%1,%2,%3}, [%4];"
                 : "=r"(r[0]), "=r"(r[1]), "=r"(r[2]), "=r"(r[3]) : "r"(a));
}
__device__ __forceinline__ void ldm_x4t(uint32_t* r, uint32_t a){
    asm volatile("ldmatrix.sync.aligned.m8n8.x4.trans.shared.b16 {%0,%1,%2,%3}, [%4];"
                 : "=r"(r[0]), "=r"(r[1]), "=r"(r[2]), "=r"(r[3]) : "r"(a));
}
__device__ __forceinline__ void ldm_x2t(uint32_t* r, uint32_t a){
    asm volatile("ldmatrix.sync.aligned.m8n8.x2.trans.shared.b16 {%0,%1}, [%2];"
                 : "=r"(r[0]), "=r"(r[1]) : "r"(a));
}
__device__ __forceinline__ void mma16816(float* d, const uint32_t* a, const uint32_t* b){
    asm volatile("mma.sync.aligned.m16n8k16.row.col.f32.bf16.bf16.f32 "
                 "{%0,%1,%2,%3}, {%4,%5,%6,%7}, {%8,%9}, {%0,%1,%2,%3};"
                 : "+f"(d[0]), "+f"(d[1]), "+f"(d[2]), "+f"(d[3])
                 : "r"(a[0]), "r"(a[1]), "r"(a[2]), "r"(a[3]), "r"(b[0]), "r"(b[1]));
}
__device__ __forceinline__ bf bfc(float x){ return __float2bfloat16(x); }
__device__ __forceinline__ uint32_t pack_bf(float x, float y){
    __nv_bfloat162 h; h.x = __float2bfloat16(x); h.y = __float2bfloat16(y);
    return *reinterpret_cast<uint32_t*>(&h);
}
__device__ __forceinline__ float ex2f(float x){
    float r; asm("ex2.approx.ftz.f32 %0, %1;" : "=f"(r) : "f"(x)); return r;
}

// ------------------------- merged cast kernel -------------------------
// y 0..3: A inputs; 4..8: weights; 9: comb = ttm | (clsm!=0)<<1
__global__ void castAll_k(const float* __restrict__ a0, const float* __restrict__ a1,
                          const float* __restrict__ a2, const float* __restrict__ a3,
                          const float* __restrict__ w0, const float* __restrict__ w1,
                          const float* __restrict__ w2, const float* __restrict__ w3,
                          const float* __restrict__ w4,
                          const unsigned char* __restrict__ ttm, const float* __restrict__ clsm,
                          bf* __restrict__ outA, bf* __restrict__ outW,
                          unsigned char* __restrict__ comb)
{
    int y = blockIdx.y;
    long long i4 = ((long long)blockIdx.x * 256 + threadIdx.x) * 4;
    if (y == 9){
        uchar4 tm = *(const uchar4*)(ttm + i4);
        float4 cl = *(const float4*)(clsm + (i4 & 0xFFFFF));
        uchar4 o;
        o.x = (tm.x ? 1 : 0) | (cl.x != 0.f ? 2 : 0);
        o.y = (tm.y ? 1 : 0) | (cl.y != 0.f ? 2 : 0);
        o.z = (tm.z ? 1 : 0) | (cl.z != 0.f ? 2 : 0);
        o.w = (tm.w ? 1 : 0) | (cl.w != 0.f ? 2 : 0);
        *(uchar4*)(comb + i4) = o;
        return;
    }
    const float* in; bf* o;
    if (y < 4){
        in = (y == 0) ? a0 : (y == 1) ? a1 : (y == 2) ? a2 : a3;
        o  = outA + (long long)y * 2048 * 1024;
    } else {
        if (blockIdx.x >= 1024) return;
        int yw = y - 4;
        in = (yw == 0) ? w0 : (yw == 1) ? w1 : (yw == 2) ? w2 : (yw == 3) ? w3 : w4;
        o  = outW + (long long)yw * 1024 * 1024;
    }
    float4 v = *(const float4*)(in + i4);
    __nv_bfloat162 p, q;
    p.x = bfc(v.x); p.y = bfc(v.y); q.x = bfc(v.z); q.y = bfc(v.w);
    *(__nv_bfloat162*)(o + i4)     = p;
    *(__nv_bfloat162*)(o + i4 + 2) = q;
}

// ------------------------- generic bf16 GEMM (proj / outproj) ------------------
template<int BN, int NT_, int EPI>
__global__ __launch_bounds__(256, 2)
void tg(const bf* __restrict__ A, const bf* __restrict__ B,
        const float* __restrict__ bias, const float* __restrict__ bias2,
        float* __restrict__ Cf, bf* __restrict__ Cb,
        int K, int lda, int ldb, int ldc)
{
    constexpr int NS = 4;
    constexpr int ASZ = 128 * 40;
    constexpr int BSTR = BN + 8;
    constexpr int BSZ = 32 * BSTR;
    extern __shared__ __align__(16) bf dyn[];
    bf* Asm = dyn;
    bf* Bsm = dyn + NS * ASZ;

    const int m0 = blockIdx.y * 128;
    int n0 = blockIdx.x * BN;
    const int z = blockIdx.z;
    int zi = 0;
    if (EPI == 6){ zi = z; A += (long long)zi * 2048 * 1024; B += (long long)zi * 1024 * 1024; }

    const int t = threadIdx.x, lane = t & 31, warp = t >> 5, wm = warp >> 2, wn = warp & 3;

    float acc[4][NT_][4];
    #pragma unroll
    for (int a = 0; a < 4; ++a)
        #pragma unroll
        for (int b = 0; b < NT_; ++b)
            #pragma unroll
            for (int c = 0; c < 4; ++c) acc[a][b][c] = 0.f;

    auto loadA = [&](int s, int k0){
        #pragma unroll
        for (int q = 0; q < 2; ++q){
            int c = t * 2 + q, row = c >> 2, seg = c & 3;
            cp16(cvta_s(Asm + s * ASZ + row * 40 + seg * 8),
                 A + (long long)(m0 + row) * lda + k0 + seg * 8);
        }
    };
    auto loadB = [&](int s, int k0){
        constexpr int CPR = BN / 8;
        #pragma unroll
        for (int q = 0; q < (32 * CPR) / 256; ++q){
            int c = t * ((32 * CPR) / 256) + q, row = c / CPR, seg = c % CPR;
            cp16(cvta_s(Bsm + s * BSZ + row * BSTR + seg * 8),
                 B + (long long)(k0 + row) * ldb + n0 + seg * 8);
        }
    };

    const int KT = K / 32;
    loadA(0, 0); loadB(0, 0);
    asm volatile("cp.async.commit_group;");
    if (KT > 1){ loadA(1, 32); loadB(1, 32); }
    asm volatile("cp.async.commit_group;");
    if (KT > 2){ loadA(2, 64); loadB(2, 64); }
    asm volatile("cp.async.commit_group;");

    for (int kt = 0; kt < KT; ++kt){
        asm volatile("cp.async.wait_group 2;");
        __syncthreads();
        int kn = kt + 3;
        if (kn < KT){ loadA(kn & 3, kn * 32); loadB(kn & 3, kn * 32); }
        asm volatile("cp.async.commit_group;");

        const int s = kt & 3;
        const uint32_t aBase = cvta_s(Asm + s * ASZ) + ((wm * 64 + (lane & 15)) * 40) * 2;
        const uint32_t bBase = cvta_s(Bsm + s * BSZ);
        #pragma unroll
        for (int ks = 0; ks < 32; ks += 16){
            uint32_t af[4][4], bfrg[NT_][2];
            #pragma unroll
            for (int mt = 0; mt < 4; ++mt)
                ldm_x4(af[mt], aBase + (mt * 16 * 40 + ks + (lane >> 4) * 8) * 2);
            #pragma unroll
            for (int nt = 0; nt < NT_; ++nt)
                ldm_x2t(bfrg[nt], bBase + (((ks + (lane & 15)) * BSTR + wn * (BN / 4) + nt * 8)) * 2);
            #pragma unroll
            for (int mt = 0; mt < 4; ++mt)
                #pragma unroll
                for (int nt = 0; nt < NT_; ++nt) mma16816(acc[mt][nt], af[mt], bfrg[nt]);
        }
    }

    #pragma unroll
    for (int mt = 0; mt < 4; ++mt)
      #pragma unroll
      for (int r2 = 0; r2 < 2; ++r2){
        const int i = m0 + wm * 64 + mt * 16 + (lane >> 2) + r2 * 8;
        #pragma unroll
        for (int nt = 0; nt < NT_; ++nt)
          #pragma unroll
          for (int c2 = 0; c2 < 2; ++c2){
            const int j = n0 + wn * (BN / 4) + nt * 8 + ((lane & 3) << 1) + c2;
            float v = acc[mt][nt][r2 * 2 + c2];
            if (EPI == 6){
                if (zi == 0) v *= SCALE * LOG2E;      // q: fold softmax log2e
                else if (zi == 1) v += bias[j];
                else if (zi == 2) v += bias2[j];
                Cb[(long long)zi * 2048 * 1024 + (long long)i * 1024 + j] = bfc(v);
            } else { // EPI 4
                Cf[(long long)i * ldc + j] = v + bias[j];
            }
          }
      }
}

// ------------------------- fused flash attention kernel ----------------------
// R12 structure + rrt/rwkm staged in smem + base-2 exponent (log2e pre-folded).
__global__ __launch_bounds__(256)
void fattn_k(const bf* __restrict__ q16, const bf* __restrict__ k16,
             const bf* __restrict__ v16, const bf* __restrict__ rh16,
             const float* __restrict__ rwkm, const float* __restrict__ rrt,
             const float* __restrict__ ttd, const unsigned char* __restrict__ comb,
             bf* __restrict__ av16)
{
    extern __shared__ __align__(16) bf dyn[];
    bf* qs  = dyn;                 // 128*72
    bf* ks  = dyn + 9216;          // 2 x 128*72
    bf* vs  = dyn + 27648;         // 2 x 128*72
    bf* rhs = dyn + 46080;         // 256*72 ring (phys row = r & 255)
    bf* Pcb = dyn + 64512;         // 128 x PSTRB bf16
    float* rws = (float*)(dyn + 64512 + 128 * PSTRB);   // 1024 floats
    float* rrs = rws + 1024;                             // 1152 floats

    const int i0 = blockIdx.x * 128;
    const int z  = blockIdx.y, bb = z >> 4, nn = z & 15;
    const int t = threadIdx.x, lane = t & 31, w = t >> 5;
    bf* Pw = Pcb + w * 16 * PSTRB;
    const int tbase = 896 - i0;

    const bf* qg = q16 + ((long long)(bb * 1024 + i0)) * 1024 + nn * 64;

    auto loadKV = [&](int buf, int j0){
        const bf* kg = k16 + ((long long)(bb * 1024 + j0)) * 1024 + nn * 64;
        const bf* vg = v16 + ((long long)(bb * 1024 + j0)) * 1024 + nn * 64;
        #pragma unroll
        for (int qq = 0; qq < 4; ++qq){
            int c = qq * 256 + t, row = c >> 3, seg = c & 7;
            cp16(cvta_s(ks + buf * 9216 + row * 72 + seg * 8), kg + (long long)row * 1024 + seg * 8);
        }
        #pragma unroll
        for (int qq = 0; qq < 4; ++qq){
            int c = qq * 256 + t, row = c >> 3, seg = c & 7;
            cp16(cvta_s(vs + buf * 9216 + row * 72 + seg * 8), vg + (long long)row * 1024 + seg * 8);
        }
    };
    auto loadRH128 = [&](int t0){
        #pragma unroll
        for (int qq = 0; qq < 4; ++qq){
            int c = qq * 256 + t, row = c >> 3, seg = c & 7;
            int tr = t0 + row;
            cp16(cvta_s(rhs + (tr & 255) * 72 + seg * 8),
                 rh16 + (long long)tr * 1024 + nn * 64 + seg * 8);
        }
    };

    #pragma unroll
    for (int qq = 0; qq < 4; ++qq){
        int c = qq * 256 + t, row = c >> 3, seg = c & 7;
        cp16(cvta_s(qs + row * 72 + seg * 8), qg + (long long)row * 1024 + seg * 8);
    }
    loadKV(0, 0);
    loadRH128(tbase);
    loadRH128(tbase + 128);
    // stage rwkm row (1024 floats) and rrt window (1152 floats)
    cp16(cvta_s(rws + t * 4), rwkm + (long long)z * 1024 + t * 4);
    {
        const float* rrg = rrt + nn * Rc + tbase;
        #pragma unroll
        for (int qq = 0; qq < 2; ++qq){
            int c = qq * 256 + t;
            if (c < 288) cp16(cvta_s(rrs + c * 4), rrg + c * 4);
        }
    }
    asm volatile("cp.async.commit_group;");
    asm volatile("cp.async.wait_group 0;");
    __syncthreads();

    const uint32_t aBase = cvta_s(qs) + ((w * 16 + (lane & 15)) * 72 + (lane >> 4) * 8) * 2;
    const uint32_t rBase = cvta_s(rhs);

    uint32_t afq[4][4];
    #pragma unroll
    for (int s = 0; s < 4; ++s) ldm_x4(afq[s], aBase + (s * 16) * 2);

    float accO[8][4];
    #pragma unroll
    for (int a = 0; a < 8; ++a){ accO[a][0] = 0.f; accO[a][1] = 0.f; accO[a][2] = 0.f; accO[a][3] = 0.f; }
    float lsumA = 0.f, lsumB = 0.f;

    const int rl0 = lane >> 2;
    const int iA = i0 + w * 16 + rl0, iB = iA + 8;
    const long long tba = ((long long)(bb * 1024 + iA) * 16 + nn) * 2;
    const long long tbb = ((long long)(bb * 1024 + iB) * 16 + nn) * 2;
    const float tdA0 = ttd[tba], tdA1 = ttd[tba + 1];
    const float tdB0 = ttd[tbb], tdB1 = ttd[tbb + 1];
    const int nt0 = 14 - 2 * w;
    const int bnOff = (lane & 7) + ((lane >> 4) << 3);
    const int bkOff = ((lane >> 3) & 1) << 3;

    for (int jt = 0; jt < 8; ++jt){
        const int j0 = jt * 128;
        const int tb0 = tbase + j0;
        const int buf = jt & 1;

        if (jt > 0){ asm volatile("cp.async.wait_group 0;"); __syncthreads(); }

        if (jt < 7){
            loadKV(buf ^ 1, j0 + 128);
            asm volatile("cp.async.commit_group;");
        }

        // ---- band-limited pos mma over ring (18 tiles, 3 groups of 6) ----
        #pragma unroll
        for (int g = 0; g < 3; ++g){
            float accP[6][4];
            #pragma unroll
            for (int a = 0; a < 6; ++a){ accP[a][0]=0.f; accP[a][1]=0.f; accP[a][2]=0.f; accP[a][3]=0.f; }
            #pragma unroll
            for (int s = 0; s < 4; ++s){
                #pragma unroll
                for (int u = 0; u < 3; ++u){
                    int ntp = nt0 + g * 6 + u * 2;
                    uint32_t b4[4];
                    ldm_x4(b4, rBase + (((unsigned)(tb0 + ntp * 8 + bnOff) & 255u) * 72 + s * 16 + bkOff) * 2);
                    mma16816(accP[2 * u],     afq[s], b4);
                    mma16816(accP[2 * u + 1], afq[s], b4 + 2);
                }
            }
            #pragma unroll
            for (int u = 0; u < 6; ++u){
                int nt = nt0 + g * 6 + u;
                #pragma unroll
                for (int c = 0; c < 4; ++c){
                    int rl = rl0 + ((c >> 1) << 3);
                    int di = w * 16 + rl;
                    int ct = nt * 8 + ((lane & 3) << 1) + (c & 1);
                    int dj = ct - 128 + di;
                    if (dj >= 0 && dj < 128)
                        Pw[rl * PSTRB + dj] = bfc(accP[u][c] + rrs[j0 + ct]);
                }
            }
        }
        __syncwarp();

        // ---- content mma (16 tiles via x4 loads) ----
        const uint32_t kBase = cvta_s(ks + buf * 9216);
        float accC[16][4];
        #pragma unroll
        for (int a = 0; a < 16; ++a){ accC[a][0]=0.f; accC[a][1]=0.f; accC[a][2]=0.f; accC[a][3]=0.f; }
        #pragma unroll
        for (int s = 0; s < 4; ++s){
            #pragma unroll
            for (int np = 0; np < 8; ++np){
                uint32_t b4[4];
                ldm_x4(b4, kBase + ((np * 16 + bnOff) * 72 + s * 16 + bkOff) * 2);
                mma16816(accC[2 * np],     afq[s], b4);
                mma16816(accC[2 * np + 1], afq[s], b4 + 2);
            }
        }

        __syncthreads();
        if (jt < 7){
            loadRH128(tb0 + 256);
            asm volatile("cp.async.commit_group;");
        }

        // ---- assemble scores, exp2, pack ----
        uint32_t pkA[16], pkB[16];
        const unsigned char* cmA = comb + (long long)(bb * 1024 + iA) * 1024 + j0;
        const unsigned char* cmB = comb + (long long)(bb * 1024 + iB) * 1024 + j0;
        #pragma unroll
        for (int nt = 0; nt < 16; ++nt){
            const int djp = nt * 8 + ((lane & 3) << 1);
            float2 rw = *(const float2*)(rws + j0 + djp);
            {
                uchar2 cm = *(const uchar2*)(cmA + djp);
                __nv_bfloat162 pb = *(const __nv_bfloat162*)(&Pw[rl0 * PSTRB + djp]);
                float clx = (cm.x & 2) ? 1.f : 0.f, cly = (cm.y & 2) ? 1.f : 0.f;
                float t0 = (cm.x & 1) ? tdA1 : tdA0, t1 = (cm.y & 1) ? tdA1 : tdA0;
                float e0 = ex2f(accC[nt][0] + rw.x + (__bfloat162float(pb.x) + t0) * clx);
                float e1 = ex2f(accC[nt][1] + rw.y + (__bfloat162float(pb.y) + t1) * cly);
                lsumA += e0 + e1;
                pkA[nt] = pack_bf(e0, e1);
            }
            {
                uchar2 cm = *(const uchar2*)(cmB + djp);
                __nv_bfloat162 pb = *(const __nv_bfloat162*)(&Pw[(rl0 + 8) * PSTRB + djp]);
                float clx = (cm.x & 2) ? 1.f : 0.f, cly = (cm.y & 2) ? 1.f : 0.f;
                float t0 = (cm.x & 1) ? tdB1 : tdB0, t1 = (cm.y & 1) ? tdB1 : tdB0;
                float e0 = ex2f(accC[nt][2] + rw.x + (__bfloat162float(pb.x) + t0) * clx);
                float e1 = ex2f(accC[nt][3] + rw.y + (__bfloat162float(pb.y) + t1) * cly);
                lsumB += e0 + e1;
                pkB[nt] = pack_bf(e0, e1);
            }
        }

        // ---- PV mma ----
        const uint32_t vBase = cvta_s(vs + buf * 9216);
        #pragma unroll
        for (int kb = 0; kb < 8; ++kb){
            uint32_t pf[4];
            pf[0] = pkA[2 * kb];     pf[1] = pkB[2 * kb];
            pf[2] = pkA[2 * kb + 1]; pf[3] = pkB[2 * kb + 1];
            #pragma unroll
            for (int np = 0; np < 4; ++np){
                uint32_t b4[4];
                ldm_x4t(b4, vBase + ((kb * 16 + (lane & 15)) * 72 + np * 16 + (lane >> 4) * 8) * 2);
                mma16816(accO[2 * np],     pf, b4);
                mma16816(accO[2 * np + 1], pf, b4 + 2);
            }
        }
    }

    // ---- finalize ----
    lsumA += __shfl_xor_sync(0xffffffffu, lsumA, 1);
    lsumA += __shfl_xor_sync(0xffffffffu, lsumA, 2);
    lsumB += __shfl_xor_sync(0xffffffffu, lsumB, 1);
    lsumB += __shfl_xor_sync(0xffffffffu, lsumB, 2);
    float invA = 1.0f / lsumA, invB = 1.0f / lsumB;
    int rA = bb * 1024 + iA, rB = bb * 1024 + iB;
    #pragma unroll
    for (int nt = 0; nt < 8; ++nt){
        int col = nn * 64 + nt * 8 + ((lane & 3) << 1);
        __nv_bfloat162 p0, p1;
        p0.x = bfc(accO[nt][0] * invA); p0.y = bfc(accO[nt][1] * invA);
        p1.x = bfc(accO[nt][2] * invB); p1.y = bfc(accO[nt][3] * invB);
        *(__nv_bfloat162*)(av16 + (long long)rA * 1024 + col) = p0;
        *(__nv_bfloat162*)(av16 + (long long)rB * 1024 + col) = p1;
    }
}

// ------------------------- merged dot kernels (log2e pre-folded) --------------
__global__ void dots_k(const bf* __restrict__ q16, const bf* __restrict__ k16,
                       const bf* __restrict__ rh16,
                       const float* __restrict__ rwb, const float* __restrict__ rrb,
                       const float* __restrict__ rsb, const float* __restrict__ seg,
                       const int* __restrict__ amask,
                       float* __restrict__ rwkm, float* __restrict__ rrt, float* __restrict__ ttd)
{
    int gw = (blockIdx.x * blockDim.x + threadIdx.x) >> 5;
    int lane = threadIdx.x & 31;
    if (blockIdx.y == 0){
        int zz = gw >> 10, j = gw & (Sc - 1);
        int b = zz >> 4, n = zz & 15;
        const bf* kp = k16 + ((long long)(b * 1024 + j)) * 1024 + n * 64;
        float d = 0.f;
        #pragma unroll
        for (int h = lane; h < Hc; h += 32) d += rwb[n * Hc + h] * __bfloat162float(kp[h]);
        #pragma unroll
        for (int o = 16; o; o >>= 1) d += __shfl_down_sync(0xffffffffu, d, o);
        if (lane == 0)
            rwkm[gw] = (d * SCALE - INFV * (1.0f - (float)amask[b * Sc + j])) * LOG2E;
    } else if (blockIdx.y == 1){
        int n = gw >> 11, tt2 = gw & (Rc - 1);
        const bf* rp = rh16 + (long long)tt2 * 1024 + n * 64;
        float d = 0.f;
        #pragma unroll
        for (int h = lane; h < Hc; h += 32) d += rrb[n * Hc + h] * __bfloat162float(rp[h]);
        #pragma unroll
        for (int o = 16; o; o >>= 1) d += __shfl_down_sync(0xffffffffu, d, o);
        if (lane == 0) rrt[gw] = d * SCALE * LOG2E;
    } else {
        int n = gw & 15;
        long long bi = gw >> 4;
        const bf* qp = q16 + bi * 1024 + n * 64;   // q16 already carries LOG2E
        float d0 = 0.f, d1 = 0.f, s0 = 0.f, s1 = 0.f;
        #pragma unroll
        for (int h = lane; h < Hc; h += 32){
            float e0 = seg[n * Hc + h], e1 = seg[Nc * Hc + n * Hc + h];
            float qv = __bfloat162float(qp[h]), rv = rsb[n * Hc + h];
            d0 += qv * e0; d1 += qv * e1; s0 += rv * e0; s1 += rv * e1;
        }
        #pragma unroll
        for (int o = 16; o; o >>= 1){
            d0 += __shfl_down_sync(0xffffffffu, d0, o);
            d1 += __shfl_down_sync(0xffffffffu, d1, o);
            s0 += __shfl_down_sync(0xffffffffu, s0, o);
            s1 += __shfl_down_sync(0xffffffffu, s1, o);
        }
        if (lane == 0){
            ttd[2 * gw]     = d0 + LOG2E * SCALE * s0;
            ttd[2 * gw + 1] = d1 + LOG2E * SCALE * s1;
        }
    }
}

// ------------------------- residual + LayerNorm -------------------------
__global__ void ln_k(const float* __restrict__ query, const float* __restrict__ ao,
                     const float* __restrict__ gamma, const float* __restrict__ beta,
                     float* __restrict__ out){
    __shared__ float red[256];
    long long base = (long long)blockIdx.x * Dc;
    int t = threadIdx.x;
    float x[4]; float s = 0.f;
    #pragma unroll
    for (int u = 0; u < 4; ++u){ x[u] = query[base + t + u * 256] + ao[base + t + u * 256]; s += x[u]; }
    red[t] = s; __syncthreads();
    #pragma unroll
    for (int o = 128; o; o >>= 1){ if (t < o) red[t] += red[t + o]; __syncthreads(); }
    float mu = red[0] * (1.0f / Dc); __syncthreads();
    float s2 = 0.f;
    #pragma unroll
    for (int u = 0; u < 4; ++u){ float d = x[u] - mu; s2 += d * d; }
    red[t] = s2; __syncthreads();
    #pragma unroll
    for (int o = 128; o; o >>= 1){ if (t < o) red[t] += red[t + o]; __syncthreads(); }
    float inv = rsqrtf(red[0] * (1.0f / Dc) + EPSV);
    #pragma unroll
    for (int u = 0; u < 4; ++u){
        int c = t + u * 256;
        out[base + c] = (x[u] - mu) * inv * gamma[c] + beta[c];
    }
}

// ------------------------- driver -------------------------
extern "C" void kernel_launch(void* const* d_in, const int* in_sizes, int n_in,
                              void* d_out, int out_size)
{
    const float* query = (const float*)d_in[0];
    const float* key   = (const float*)d_in[1];
    const float* value = (const float*)d_in[2];
    const float* r     = (const float*)d_in[3];
    const float* clsm  = (const float*)d_in[4];
    const float* Wq    = (const float*)d_in[5];
    const float* Wk    = (const float*)d_in[6];
    const float* bk    = (const float*)d_in[7];
    const float* Wv    = (const float*)d_in[8];
    const float* bv    = (const float*)d_in[9];
    const float* Wo    = (const float*)d_in[10];
    const float* bo    = (const float*)d_in[11];
    const float* rwb   = (const float*)d_in[12];
    const float* rrb   = (const float*)d_in[13];
    const float* rkern = (const float*)d_in[14];
    const float* rsb   = (const float*)d_in[15];
    const float* seg   = (const float*)d_in[16];
    const float* gamma = (const float*)d_in[17];
    const float* beta  = (const float*)d_in[18];
    const unsigned char* ttm = (const unsigned char*)d_in[19];
    const int*   amask = (const int*)d_in[20];
    float* out = (float*)d_out;

    bf *in16, *w16, *proj, *av16;
    float *ao, *rwk, *rrt, *ttd;
    unsigned char* comb;
    cudaGetSymbolAddress((void**)&in16, g_in16);
    cudaGetSymbolAddress((void**)&w16,  g_w16);
    cudaGetSymbolAddress((void**)&proj, g_proj);
    cudaGetSymbolAddress((void**)&av16, g_av16);
    cudaGetSymbolAddress((void**)&ao,   g_ao);
    cudaGetSymbolAddress((void**)&rwk,  g_rwk);
    cudaGetSymbolAddress((void**)&rrt,  g_rrt);
    cudaGetSymbolAddress((void**)&ttd,  g_ttd);
    cudaGetSymbolAddress((void**)&comb, g_comb);

    bf* q16  = proj;
    bf* k16  = proj + 1LL * 2048 * 1024;
    bf* v16  = proj + 2LL * 2048 * 1024;
    bf* rh16 = proj + 3LL * 2048 * 1024;

    auto k6 = tg<128, 4, 6>;
    auto k4 = tg<128, 4, 4>;
    cudaFuncSetAttribute(k6, cudaFuncAttributeMaxDynamicSharedMemorySize, 75776);
    cudaFuncSetAttribute(k4, cudaFuncAttributeMaxDynamicSharedMemorySize, 75776);
    cudaFuncSetAttribute(fattn_k, cudaFuncAttributeMaxDynamicSharedMemorySize, 172544);

    // 0) casts + comb (merged)
    castAll_k<<<dim3(2048, 10), 256>>>(query, key, value, r, Wq, Wk, Wv, rkern, Wo,
                                       ttm, clsm, in16, w16, comb);

    // 1) merged projections
    k6<<<dim3(8, 16, 4), 256, 75776>>>(in16, w16, bk, bv, nullptr, proj,
        1024, 1024, 1024, 0);

    // 2) merged bias-dot tables (mask + log2e folded)
    dots_k<<<dim3(4096, 3), 256>>>(q16, k16, rh16, rwb, rrb, rsb, seg, amask, rwk, rrt, ttd);

    // 3) fused scores + softmax + PV
    fattn_k<<<dim3(8, 32), 256, 172544>>>(q16, k16, v16, rh16,
        rwk, rrt, ttd, comb, av16);

    // 4) output projection + bias
    k4<<<dim3(8, 16, 1), 256, 75776>>>(av16, w16 + 4LL * 1024 * 1024, bo, nullptr, ao, nullptr,
        1024, 1024, 1024, 1024);

    // 5) residual + LayerNorm
    ln_k<<<Bc * Sc, 256>>>(query, ao, gamma, beta, out);

    (void)in_sizes; (void)n_in; (void)out_size;
}

// round 14
// speedup vs baseline: 1.0367x; 1.0367x over previous
#include <cuda_runtime.h>
#include <cuda_bf16.h>
#include <math.h>
#include <stdint.h>

#define Bc 2
#define Sc 1024
#define Dc 1024
#define Nc 16
#define Hc 64
#define NHc 1024
#define Rc 2048
#define SCALE 0.125f
#define INFV 1000000.0f
#define EPSV 1e-9f
#define PSTRB 136

typedef __nv_bfloat16 bf;

// ------------------------- scratch -------------------------
__device__ bf g_in16[4 * 2048 * 1024];
__device__ bf g_w16 [5 * 1024 * 1024];
__device__ bf g_proj[4 * 2048 * 1024];
__device__ bf g_av16[2048 * 1024];
__device__ float g_ao[2048 * 1024];
__device__ float g_rwk[32 * 1024];
__device__ float g_rrt[16 * 2048];
__device__ float g_ttd[2048 * 16 * 2];
__device__ unsigned char g_comb[2 * 1024 * 1024];   // ttm | (clsm!=0)<<1

// ------------------------- helpers -------------------------
__device__ __forceinline__ uint32_t cvta_s(const void* p){ return (uint32_t)__cvta_generic_to_shared(p); }
__device__ __forceinline__ void cp16(uint32_t d, const void* s){
    asm volatile("cp.async.cg.shared.global [%0], [%1], 16;" :: "r"(d), "l"(s));
}
__device__ __forceinline__ void ldm_x4(uint32_t* r, uint32_t a){
    asm volatile("ldmatrix.sync.aligned.m8n8.x4.shared.b16 {%0,%1,%2,%3}, [%4];"
                 : "=r"(r[0]), "=r"(r[1]), "=r"(r[2]), "=r"(r[3]) : "r"(a));
}
__device__ __forceinline__ void ldm_x4t(uint32_t* r, uint32_t a){
    asm volatile("ldmatrix.sync.aligned.m8n8.x4.trans.shared.b16 {%0,%1,%2,%3}, [%4];"
                 : "=r"(r[0]), "=r"(r[1]), "=r"(r[2]), "=r"(r[3]) : "r"(a));
}
__device__ __forceinline__ void ldm_x2t(uint32_t* r, uint32_t a){
    asm volatile("ldmatrix.sync.aligned.m8n8.x2.trans.shared.b16 {%0,%1}, [%2];"
                 : "=r"(r[0]), "=r"(r[1]) : "r"(a));
}
__device__ __forceinline__ void mma16816(float* d, const uint32_t* a, const uint32_t* b){
    asm volatile("mma.sync.aligned.m16n8k16.row.col.f32.bf16.bf16.f32 "
                 "{%0,%1,%2,%3}, {%4,%5,%6,%7}, {%8,%9}, {%0,%1,%2,%3};"
                 : "+f"(d[0]), "+f"(d[1]), "+f"(d[2]), "+f"(d[3])
                 : "r"(a[0]), "r"(a[1]), "r"(a[2]), "r"(a[3]), "r"(b[0]), "r"(b[1]));
}
__device__ __forceinline__ bf bfc(float x){ return __float2bfloat16(x); }
__device__ __forceinline__ uint32_t pack_bf(float x, float y){
    __nv_bfloat162 h; h.x = __float2bfloat16(x); h.y = __float2bfloat16(y);
    return *reinterpret_cast<uint32_t*>(&h);
}

// ------------------------- merged cast kernel (MLP=4) -------------------------
// grid (512, 10). y 0..3: A inputs (2M elem, 4 f4/thr); 4..8: W (1M, 2 f4/thr);
// 9: comb (2M bytes, 4 uchar4/thr)
__global__ void castAll_k(const float* __restrict__ a0, const float* __restrict__ a1,
                          const float* __restrict__ a2, const float* __restrict__ a3,
                          const float* __restrict__ w0, const float* __restrict__ w1,
                          const float* __restrict__ w2, const float* __restrict__ w3,
                          const float* __restrict__ w4,
                          const unsigned char* __restrict__ ttm, const float* __restrict__ clsm,
                          bf* __restrict__ outA, bf* __restrict__ outW,
                          unsigned char* __restrict__ comb)
{
    const int y = blockIdx.y;
    const long long tid = (long long)blockIdx.x * 256 + threadIdx.x;   // 0..131071
    if (y == 9){
        uchar4 tm[4]; float4 cl[4];
        #pragma unroll
        for (int u = 0; u < 4; ++u){
            long long e = (tid + (long long)u * 131072) * 4;
            tm[u] = *(const uchar4*)(ttm + e);
            cl[u] = *(const float4*)(clsm + (e & 0xFFFFF));
        }
        #pragma unroll
        for (int u = 0; u < 4; ++u){
            long long e = (tid + (long long)u * 131072) * 4;
            uchar4 o;
            o.x = (tm[u].x ? 1 : 0) | (cl[u].x != 0.f ? 2 : 0);
            o.y = (tm[u].y ? 1 : 0) | (cl[u].y != 0.f ? 2 : 0);
            o.z = (tm[u].z ? 1 : 0) | (cl[u].z != 0.f ? 2 : 0);
            o.w = (tm[u].w ? 1 : 0) | (cl[u].w != 0.f ? 2 : 0);
            *(uchar4*)(comb + e) = o;
        }
        return;
    }
    if (y < 4){
        const float* in = (y == 0) ? a0 : (y == 1) ? a1 : (y == 2) ? a2 : a3;
        bf* o = outA + (long long)y * 2097152;
        float4 v[4];
        #pragma unroll
        for (int u = 0; u < 4; ++u)
            v[u] = *(const float4*)(in + (tid + (long long)u * 131072) * 4);
        #pragma unroll
        for (int u = 0; u < 4; ++u){
            long long e = (tid + (long long)u * 131072) * 4;
            __nv_bfloat162 p, q;
            p.x = bfc(v[u].x); p.y = bfc(v[u].y); q.x = bfc(v[u].z); q.y = bfc(v[u].w);
            *(__nv_bfloat162*)(o + e)     = p;
            *(__nv_bfloat162*)(o + e + 2) = q;
        }
    } else {
        int yw = y - 4;
        const float* in = (yw == 0) ? w0 : (yw == 1) ? w1 : (yw == 2) ? w2 : (yw == 3) ? w3 : w4;
        bf* o = outW + (long long)yw * 1048576;
        float4 v[2];
        #pragma unroll
        for (int u = 0; u < 2; ++u)
            v[u] = *(const float4*)(in + (tid + (long long)u * 131072) * 4);
        #pragma unroll
        for (int u = 0; u < 2; ++u){
            long long e = (tid + (long long)u * 131072) * 4;
            __nv_bfloat162 p, q;
            p.x = bfc(v[u].x); p.y = bfc(v[u].y); q.x = bfc(v[u].z); q.y = bfc(v[u].w);
            *(__nv_bfloat162*)(o + e)     = p;
            *(__nv_bfloat162*)(o + e + 2) = q;
        }
    }
}

// ------------------------- generic bf16 GEMM (proj / outproj) ------------------
template<int BN, int NT_, int EPI>
__global__ __launch_bounds__(256, 2)
void tg(const bf* __restrict__ A, const bf* __restrict__ B,
        const float* __restrict__ bias, const float* __restrict__ bias2,
        float* __restrict__ Cf, bf* __restrict__ Cb,
        int K, int lda, int ldb, int ldc)
{
    constexpr int NS = 4;
    constexpr int ASZ = 128 * 40;
    constexpr int BSTR = BN + 8;
    constexpr int BSZ = 32 * BSTR;
    extern __shared__ __align__(16) bf dyn[];
    bf* Asm = dyn;
    bf* Bsm = dyn + NS * ASZ;

    const int m0 = blockIdx.y * 128;
    int n0 = blockIdx.x * BN;
    const int z = blockIdx.z;
    int zi = 0;
    if (EPI == 6){ zi = z; A += (long long)zi * 2048 * 1024; B += (long long)zi * 1024 * 1024; }

    const int t = threadIdx.x, lane = t & 31, warp = t >> 5, wm = warp >> 2, wn = warp & 3;

    float acc[4][NT_][4];
    #pragma unroll
    for (int a = 0; a < 4; ++a)
        #pragma unroll
        for (int b = 0; b < NT_; ++b)
            #pragma unroll
            for (int c = 0; c < 4; ++c) acc[a][b][c] = 0.f;

    auto loadA = [&](int s, int k0){
        #pragma unroll
        for (int q = 0; q < 2; ++q){
            int c = t * 2 + q, row = c >> 2, seg = c & 3;
            cp16(cvta_s(Asm + s * ASZ + row * 40 + seg * 8),
                 A + (long long)(m0 + row) * lda + k0 + seg * 8);
        }
    };
    auto loadB = [&](int s, int k0){
        constexpr int CPR = BN / 8;
        #pragma unroll
        for (int q = 0; q < (32 * CPR) / 256; ++q){
            int c = t * ((32 * CPR) / 256) + q, row = c / CPR, seg = c % CPR;
            cp16(cvta_s(Bsm + s * BSZ + row * BSTR + seg * 8),
                 B + (long long)(k0 + row) * ldb + n0 + seg * 8);
        }
    };

    const int KT = K / 32;
    loadA(0, 0); loadB(0, 0);
    asm volatile("cp.async.commit_group;");
    if (KT > 1){ loadA(1, 32); loadB(1, 32); }
    asm volatile("cp.async.commit_group;");
    if (KT > 2){ loadA(2, 64); loadB(2, 64); }
    asm volatile("cp.async.commit_group;");

    for (int kt = 0; kt < KT; ++kt){
        asm volatile("cp.async.wait_group 2;");
        __syncthreads();
        int kn = kt + 3;
        if (kn < KT){ loadA(kn & 3, kn * 32); loadB(kn & 3, kn * 32); }
        asm volatile("cp.async.commit_group;");

        const int s = kt & 3;
        const uint32_t aBase = cvta_s(Asm + s * ASZ) + ((wm * 64 + (lane & 15)) * 40) * 2;
        const uint32_t bBase = cvta_s(Bsm + s * BSZ);
        #pragma unroll
        for (int ks = 0; ks < 32; ks += 16){
            uint32_t af[4][4], bfrg[NT_][2];
            #pragma unroll
            for (int mt = 0; mt < 4; ++mt)
                ldm_x4(af[mt], aBase + (mt * 16 * 40 + ks + (lane >> 4) * 8) * 2);
            #pragma unroll
            for (int nt = 0; nt < NT_; ++nt)
                ldm_x2t(bfrg[nt], bBase + (((ks + (lane & 15)) * BSTR + wn * (BN / 4) + nt * 8)) * 2);
            #pragma unroll
            for (int mt = 0; mt < 4; ++mt)
                #pragma unroll
                for (int nt = 0; nt < NT_; ++nt) mma16816(acc[mt][nt], af[mt], bfrg[nt]);
        }
    }

    #pragma unroll
    for (int mt = 0; mt < 4; ++mt)
      #pragma unroll
      for (int r2 = 0; r2 < 2; ++r2){
        const int i = m0 + wm * 64 + mt * 16 + (lane >> 2) + r2 * 8;
        #pragma unroll
        for (int nt = 0; nt < NT_; ++nt)
          #pragma unroll
          for (int c2 = 0; c2 < 2; ++c2){
            const int j = n0 + wn * (BN / 4) + nt * 8 + ((lane & 3) << 1) + c2;
            float v = acc[mt][nt][r2 * 2 + c2];
            if (EPI == 6){
                if (zi == 0) v *= SCALE;
                else if (zi == 1) v += bias[j];
                else if (zi == 2) v += bias2[j];
                Cb[(long long)zi * 2048 * 1024 + (long long)i * 1024 + j] = bfc(v);
            } else { // EPI 4
                Cf[(long long)i * ldc + j] = v + bias[j];
            }
          }
      }
}

// ------------------------- fused flash attention kernel (R12 verbatim) --------
__global__ __launch_bounds__(256)
void fattn_k(const bf* __restrict__ q16, const bf* __restrict__ k16,
             const bf* __restrict__ v16, const bf* __restrict__ rh16,
             const float* __restrict__ rwkm, const float* __restrict__ rrt,
             const float* __restrict__ ttd, const unsigned char* __restrict__ comb,
             bf* __restrict__ av16)
{
    extern __shared__ __align__(16) bf dyn[];
    bf* qs  = dyn;                 // 128*72
    bf* ks  = dyn + 9216;          // 2 x 128*72
    bf* vs  = dyn + 27648;         // 2 x 128*72
    bf* rhs = dyn + 46080;         // 256*72 ring (phys row = r & 255)
    bf* Pcb = dyn + 64512;         // 128 x PSTRB bf16

    const int i0 = blockIdx.x * 128;
    const int z  = blockIdx.y, bb = z >> 4, nn = z & 15;
    const int t = threadIdx.x, lane = t & 31, w = t >> 5;
    bf* Pw = Pcb + w * 16 * PSTRB;
    const int tbase = 896 - i0;

    const bf* qg = q16 + ((long long)(bb * 1024 + i0)) * 1024 + nn * 64;

    auto loadKV = [&](int buf, int j0){
        const bf* kg = k16 + ((long long)(bb * 1024 + j0)) * 1024 + nn * 64;
        const bf* vg = v16 + ((long long)(bb * 1024 + j0)) * 1024 + nn * 64;
        #pragma unroll
        for (int qq = 0; qq < 4; ++qq){
            int c = qq * 256 + t, row = c >> 3, seg = c & 7;
            cp16(cvta_s(ks + buf * 9216 + row * 72 + seg * 8), kg + (long long)row * 1024 + seg * 8);
        }
        #pragma unroll
        for (int qq = 0; qq < 4; ++qq){
            int c = qq * 256 + t, row = c >> 3, seg = c & 7;
            cp16(cvta_s(vs + buf * 9216 + row * 72 + seg * 8), vg + (long long)row * 1024 + seg * 8);
        }
    };
    auto loadRH128 = [&](int t0){
        #pragma unroll
        for (int qq = 0; qq < 4; ++qq){
            int c = qq * 256 + t, row = c >> 3, seg = c & 7;
            int tr = t0 + row;
            cp16(cvta_s(rhs + (tr & 255) * 72 + seg * 8),
                 rh16 + (long long)tr * 1024 + nn * 64 + seg * 8);
        }
    };

    #pragma unroll
    for (int qq = 0; qq < 4; ++qq){
        int c = qq * 256 + t, row = c >> 3, seg = c & 7;
        cp16(cvta_s(qs + row * 72 + seg * 8), qg + (long long)row * 1024 + seg * 8);
    }
    loadKV(0, 0);
    loadRH128(tbase);
    loadRH128(tbase + 128);
    asm volatile("cp.async.commit_group;");
    asm volatile("cp.async.wait_group 0;");
    __syncthreads();

    const uint32_t aBase = cvta_s(qs) + ((w * 16 + (lane & 15)) * 72 + (lane >> 4) * 8) * 2;
    const uint32_t rBase = cvta_s(rhs);

    uint32_t afq[4][4];
    #pragma unroll
    for (int s = 0; s < 4; ++s) ldm_x4(afq[s], aBase + (s * 16) * 2);

    float accO[8][4];
    #pragma unroll
    for (int a = 0; a < 8; ++a){ accO[a][0] = 0.f; accO[a][1] = 0.f; accO[a][2] = 0.f; accO[a][3] = 0.f; }
    float lsumA = 0.f, lsumB = 0.f;

    const int rl0 = lane >> 2;
    const int iA = i0 + w * 16 + rl0, iB = iA + 8;
    const long long tba = ((long long)(bb * 1024 + iA) * 16 + nn) * 2;
    const long long tbb = ((long long)(bb * 1024 + iB) * 16 + nn) * 2;
    const float tdA0 = ttd[tba], tdA1 = ttd[tba + 1];
    const float tdB0 = ttd[tbb], tdB1 = ttd[tbb + 1];
    const int nt0 = 14 - 2 * w;
    const int bnOff = (lane & 7) + ((lane >> 4) << 3);
    const int bkOff = ((lane >> 3) & 1) << 3;

    for (int jt = 0; jt < 8; ++jt){
        const int j0 = jt * 128;
        const int tb0 = tbase + j0;
        const int buf = jt & 1;
        const float* rrtp = rrt + nn * Rc + tb0;

        if (jt > 0){ asm volatile("cp.async.wait_group 0;"); __syncthreads(); }

        if (jt < 7){
            loadKV(buf ^ 1, j0 + 128);
            asm volatile("cp.async.commit_group;");
        }

        // ---- band-limited pos mma over ring (18 tiles, 3 groups of 6) ----
        #pragma unroll
        for (int g = 0; g < 3; ++g){
            float accP[6][4];
            #pragma unroll
            for (int a = 0; a < 6; ++a){ accP[a][0]=0.f; accP[a][1]=0.f; accP[a][2]=0.f; accP[a][3]=0.f; }
            #pragma unroll
            for (int s = 0; s < 4; ++s){
                #pragma unroll
                for (int u = 0; u < 3; ++u){
                    int ntp = nt0 + g * 6 + u * 2;
                    uint32_t b4[4];
                    ldm_x4(b4, rBase + (((unsigned)(tb0 + ntp * 8 + bnOff) & 255u) * 72 + s * 16 + bkOff) * 2);
                    mma16816(accP[2 * u],     afq[s], b4);
                    mma16816(accP[2 * u + 1], afq[s], b4 + 2);
                }
            }
            #pragma unroll
            for (int u = 0; u < 6; ++u){
                int nt = nt0 + g * 6 + u;
                #pragma unroll
                for (int c = 0; c < 4; ++c){
                    int rl = rl0 + ((c >> 1) << 3);
                    int di = w * 16 + rl;
                    int ct = nt * 8 + ((lane & 3) << 1) + (c & 1);
                    int dj = ct - 128 + di;
                    if (dj >= 0 && dj < 128)
                        Pw[rl * PSTRB + dj] = bfc(accP[u][c] + rrtp[ct]);
                }
            }
        }
        __syncwarp();

        // ---- content mma (16 tiles via x4 loads) ----
        const uint32_t kBase = cvta_s(ks + buf * 9216);
        float accC[16][4];
        #pragma unroll
        for (int a = 0; a < 16; ++a){ accC[a][0]=0.f; accC[a][1]=0.f; accC[a][2]=0.f; accC[a][3]=0.f; }
        #pragma unroll
        for (int s = 0; s < 4; ++s){
            #pragma unroll
            for (int np = 0; np < 8; ++np){
                uint32_t b4[4];
                ldm_x4(b4, kBase + ((np * 16 + bnOff) * 72 + s * 16 + bkOff) * 2);
                mma16816(accC[2 * np],     afq[s], b4);
                mma16816(accC[2 * np + 1], afq[s], b4 + 2);
            }
        }

        __syncthreads();
        if (jt < 7){
            loadRH128(tb0 + 256);
            asm volatile("cp.async.commit_group;");
        }

        // ---- assemble scores, exp, pack ----
        uint32_t pkA[16], pkB[16];
        const float* rwp = rwkm + (long long)z * 1024 + j0;
        const unsigned char* cmA = comb + (long long)(bb * 1024 + iA) * 1024 + j0;
        const unsigned char* cmB = comb + (long long)(bb * 1024 + iB) * 1024 + j0;
        #pragma unroll
        for (int nt = 0; nt < 16; ++nt){
            const int djp = nt * 8 + ((lane & 3) << 1);
            float2 rw = *(const float2*)(rwp + djp);
            {
                uchar2 cm = *(const uchar2*)(cmA + djp);
                __nv_bfloat162 pb = *(const __nv_bfloat162*)(&Pw[rl0 * PSTRB + djp]);
                float clx = (cm.x & 2) ? 1.f : 0.f, cly = (cm.y & 2) ? 1.f : 0.f;
                float t0 = (cm.x & 1) ? tdA1 : tdA0, t1 = (cm.y & 1) ? tdA1 : tdA0;
                float e0 = __expf(accC[nt][0] + rw.x + (__bfloat162float(pb.x) + t0) * clx);
                float e1 = __expf(accC[nt][1] + rw.y + (__bfloat162float(pb.y) + t1) * cly);
                lsumA += e0 + e1;
                pkA[nt] = pack_bf(e0, e1);
            }
            {
                uchar2 cm = *(const uchar2*)(cmB + djp);
                __nv_bfloat162 pb = *(const __nv_bfloat162*)(&Pw[(rl0 + 8) * PSTRB + djp]);
                float clx = (cm.x & 2) ? 1.f : 0.f, cly = (cm.y & 2) ? 1.f : 0.f;
                float t0 = (cm.x & 1) ? tdB1 : tdB0, t1 = (cm.y & 1) ? tdB1 : tdB0;
                float e0 = __expf(accC[nt][2] + rw.x + (__bfloat162float(pb.x) + t0) * clx);
                float e1 = __expf(accC[nt][3] + rw.y + (__bfloat162float(pb.y) + t1) * cly);
                lsumB += e0 + e1;
                pkB[nt] = pack_bf(e0, e1);
            }
        }

        // ---- PV mma ----
        const uint32_t vBase = cvta_s(vs + buf * 9216);
        #pragma unroll
        for (int kb = 0; kb < 8; ++kb){
            uint32_t pf[4];
            pf[0] = pkA[2 * kb];     pf[1] = pkB[2 * kb];
            pf[2] = pkA[2 * kb + 1]; pf[3] = pkB[2 * kb + 1];
            #pragma unroll
            for (int np = 0; np < 4; ++np){
                uint32_t b4[4];
                ldm_x4t(b4, vBase + ((kb * 16 + (lane & 15)) * 72 + np * 16 + (lane >> 4) * 8) * 2);
                mma16816(accO[2 * np],     pf, b4);
                mma16816(accO[2 * np + 1], pf, b4 + 2);
            }
        }
    }

    // ---- finalize ----
    lsumA += __shfl_xor_sync(0xffffffffu, lsumA, 1);
    lsumA += __shfl_xor_sync(0xffffffffu, lsumA, 2);
    lsumB += __shfl_xor_sync(0xffffffffu, lsumB, 1);
    lsumB += __shfl_xor_sync(0xffffffffu, lsumB, 2);
    float invA = 1.0f / lsumA, invB = 1.0f / lsumB;
    int rA = bb * 1024 + iA, rB = bb * 1024 + iB;
    #pragma unroll
    for (int nt = 0; nt < 8; ++nt){
        int col = nn * 64 + nt * 8 + ((lane & 3) << 1);
        __nv_bfloat162 p0, p1;
        p0.x = bfc(accO[nt][0] * invA); p0.y = bfc(accO[nt][1] * invA);
        p1.x = bfc(accO[nt][2] * invB); p1.y = bfc(accO[nt][3] * invB);
        *(__nv_bfloat162*)(av16 + (long long)rA * 1024 + col) = p0;
        *(__nv_bfloat162*)(av16 + (long long)rB * 1024 + col) = p1;
    }
}

// ------------------------- merged dot kernels (vectorized loads) ---------------
__global__ void dots_k(const bf* __restrict__ q16, const bf* __restrict__ k16,
                       const bf* __restrict__ rh16,
                       const float* __restrict__ rwb, const float* __restrict__ rrb,
                       const float* __restrict__ rsb, const float* __restrict__ seg,
                       const int* __restrict__ amask,
                       float* __restrict__ rwkm, float* __restrict__ rrt, float* __restrict__ ttd)
{
    int gw = (blockIdx.x * blockDim.x + threadIdx.x) >> 5;
    int lane = threadIdx.x & 31;
    if (blockIdx.y == 0){
        int zz = gw >> 10, j = gw & (Sc - 1);
        int b = zz >> 4, n = zz & 15;
        const bf* kp = k16 + ((long long)(b * 1024 + j)) * 1024 + n * 64;
        __nv_bfloat162 kk = ((const __nv_bfloat162*)kp)[lane];
        float2 rw = *(const float2*)(rwb + n * Hc + 2 * lane);
        float d = rw.x * __bfloat162float(kk.x) + rw.y * __bfloat162float(kk.y);
        #pragma unroll
        for (int o = 16; o; o >>= 1) d += __shfl_down_sync(0xffffffffu, d, o);
        if (lane == 0)
            rwkm[gw] = d * SCALE - INFV * (1.0f - (float)amask[b * Sc + j]);
    } else if (blockIdx.y == 1){
        int n = gw >> 11, tt2 = gw & (Rc - 1);
        const bf* rp = rh16 + (long long)tt2 * 1024 + n * 64;
        __nv_bfloat162 rr = ((const __nv_bfloat162*)rp)[lane];
        float2 rb = *(const float2*)(rrb + n * Hc + 2 * lane);
        float d = rb.x * __bfloat162float(rr.x) + rb.y * __bfloat162float(rr.y);
        #pragma unroll
        for (int o = 16; o; o >>= 1) d += __shfl_down_sync(0xffffffffu, d, o);
        if (lane == 0) rrt[gw] = d * SCALE;
    } else {
        int n = gw & 15;
        long long bi = gw >> 4;
        const bf* qp = q16 + bi * 1024 + n * 64;
        __nv_bfloat162 qq = ((const __nv_bfloat162*)qp)[lane];
        float2 e0v = *(const float2*)(seg + n * Hc + 2 * lane);
        float2 e1v = *(const float2*)(seg + Nc * Hc + n * Hc + 2 * lane);
        float2 rv  = *(const float2*)(rsb + n * Hc + 2 * lane);
        float qx = __bfloat162float(qq.x), qy = __bfloat162float(qq.y);
        float d0 = qx * e0v.x + qy * e0v.y;
        float d1 = qx * e1v.x + qy * e1v.y;
        float s0 = rv.x * e0v.x + rv.y * e0v.y;
        float s1 = rv.x * e1v.x + rv.y * e1v.y;
        #pragma unroll
        for (int o = 16; o; o >>= 1){
            d0 += __shfl_down_sync(0xffffffffu, d0, o);
            d1 += __shfl_down_sync(0xffffffffu, d1, o);
            s0 += __shfl_down_sync(0xffffffffu, s0, o);
            s1 += __shfl_down_sync(0xffffffffu, s1, o);
        }
        if (lane == 0){
            ttd[2 * gw]     = d0 + SCALE * s0;
            ttd[2 * gw + 1] = d1 + SCALE * s1;
        }
    }
}

// ------------------------- residual + LayerNorm -------------------------
__global__ void ln_k(const float* __restrict__ query, const float* __restrict__ ao,
                     const float* __restrict__ gamma, const float* __restrict__ beta,
                     float* __restrict__ out){
    __shared__ float red[256];
    long long base = (long long)blockIdx.x * Dc;
    int t = threadIdx.x;
    float x[4]; float s = 0.f;
    #pragma unroll
    for (int u = 0; u < 4; ++u){ x[u] = query[base + t + u * 256] + ao[base + t + u * 256]; s += x[u]; }
    red[t] = s; __syncthreads();
    #pragma unroll
    for (int o = 128; o; o >>= 1){ if (t < o) red[t] += red[t + o]; __syncthreads(); }
    float mu = red[0] * (1.0f / Dc); __syncthreads();
    float s2 = 0.f;
    #pragma unroll
    for (int u = 0; u < 4; ++u){ float d = x[u] - mu; s2 += d * d; }
    red[t] = s2; __syncthreads();
    #pragma unroll
    for (int o = 128; o; o >>= 1){ if (t < o) red[t] += red[t + o]; __syncthreads(); }
    float inv = rsqrtf(red[0] * (1.0f / Dc) + EPSV);
    #pragma unroll
    for (int u = 0; u < 4; ++u){
        int c = t + u * 256;
        out[base + c] = (x[u] - mu) * inv * gamma[c] + beta[c];
    }
}

// ------------------------- driver -------------------------
extern "C" void kernel_launch(void* const* d_in, const int* in_sizes, int n_in,
                              void* d_out, int out_size)
{
    const float* query = (const float*)d_in[0];
    const float* key   = (const float*)d_in[1];
    const float* value = (const float*)d_in[2];
    const float* r     = (const float*)d_in[3];
    const float* clsm  = (const float*)d_in[4];
    const float* Wq    = (const float*)d_in[5];
    const float* Wk    = (const float*)d_in[6];
    const float* bk    = (const float*)d_in[7];
    const float* Wv    = (const float*)d_in[8];
    const float* bv    = (const float*)d_in[9];
    const float* Wo    = (const float*)d_in[10];
    const float* bo    = (const float*)d_in[11];
    const float* rwb   = (const float*)d_in[12];
    const float* rrb   = (const float*)d_in[13];
    const float* rkern = (const float*)d_in[14];
    const float* rsb   = (const float*)d_in[15];
    const float* seg   = (const float*)d_in[16];
    const float* gamma = (const float*)d_in[17];
    const float* beta  = (const float*)d_in[18];
    const unsigned char* ttm = (const unsigned char*)d_in[19];
    const int*   amask = (const int*)d_in[20];
    float* out = (float*)d_out;

    bf *in16, *w16, *proj, *av16;
    float *ao, *rwk, *rrt, *ttd;
    unsigned char* comb;
    cudaGetSymbolAddress((void**)&in16, g_in16);
    cudaGetSymbolAddress((void**)&w16,  g_w16);
    cudaGetSymbolAddress((void**)&proj, g_proj);
    cudaGetSymbolAddress((void**)&av16, g_av16);
    cudaGetSymbolAddress((void**)&ao,   g_ao);
    cudaGetSymbolAddress((void**)&rwk,  g_rwk);
    cudaGetSymbolAddress((void**)&rrt,  g_rrt);
    cudaGetSymbolAddress((void**)&ttd,  g_ttd);
    cudaGetSymbolAddress((void**)&comb, g_comb);

    bf* q16  = proj;
    bf* k16  = proj + 1LL * 2048 * 1024;
    bf* v16  = proj + 2LL * 2048 * 1024;
    bf* rh16 = proj + 3LL * 2048 * 1024;

    auto k6 = tg<128, 4, 6>;
    auto k4 = tg<128, 4, 4>;
    cudaFuncSetAttribute(k6, cudaFuncAttributeMaxDynamicSharedMemorySize, 75776);
    cudaFuncSetAttribute(k4, cudaFuncAttributeMaxDynamicSharedMemorySize, 75776);
    cudaFuncSetAttribute(fattn_k, cudaFuncAttributeMaxDynamicSharedMemorySize, 163840);

    // 0) casts + comb (merged, MLP=4)
    castAll_k<<<dim3(512, 10), 256>>>(query, key, value, r, Wq, Wk, Wv, rkern, Wo,
                                      ttm, clsm, in16, w16, comb);

    // 1) merged projections
    k6<<<dim3(8, 16, 4), 256, 75776>>>(in16, w16, bk, bv, nullptr, proj,
        1024, 1024, 1024, 0);

    // 2) merged bias-dot tables (mask folded into rwk)
    dots_k<<<dim3(4096, 3), 256>>>(q16, k16, rh16, rwb, rrb, rsb, seg, amask, rwk, rrt, ttd);

    // 3) fused scores + softmax + PV
    fattn_k<<<dim3(8, 32), 256, 163840>>>(q16, k16, v16, rh16,
        rwk, rrt, ttd, comb, av16);

    // 4) output projection + bias
    k4<<<dim3(8, 16, 1), 256, 75776>>>(av16, w16 + 4LL * 1024 * 1024, bo, nullptr, ao, nullptr,
        1024, 1024, 1024, 1024);

    // 5) residual + LayerNorm
    ln_k<<<Bc * Sc, 256>>>(query, ao, gamma, beta, out);

    (void)in_sizes; (void)n_in; (void)out_size;
}

// round 15
// speedup vs baseline: 1.1020x; 1.0630x over previous
#include <cuda_runtime.h>
#include <cuda_bf16.h>
#include <math.h>
#include <stdint.h>

#define Bc 2
#define Sc 1024
#define Dc 1024
#define Nc 16
#define Hc 64
#define NHc 1024
#define Rc 2048
#define SCALE 0.125f
#define INFV 1000000.0f
#define EPSV 1e-9f
#define PSTRB 136

typedef __nv_bfloat16 bf;

// ------------------------- scratch -------------------------
__device__ bf g_in16[4 * 2048 * 1024];
__device__ bf g_w16 [5 * 1024 * 1024];
__device__ bf g_proj[4 * 2048 * 1024];
__device__ bf g_av16[2048 * 1024];
__device__ float g_ao[2048 * 1024];
__device__ float g_rwk[32 * 1024];
__device__ float g_rrt[16 * 2048];
__device__ float g_ttd[2048 * 16 * 2];
__device__ unsigned char g_comb[2 * 1024 * 1024];

// ------------------------- helpers -------------------------
__device__ __forceinline__ uint32_t cvta_s(const void* p){ return (uint32_t)__cvta_generic_to_shared(p); }
__device__ __forceinline__ void cp16(uint32_t d, const void* s){
    asm volatile("cp.async.cg.shared.global [%0], [%1], 16;" :: "r"(d), "l"(s));
}
__device__ __forceinline__ void ldm_x4(uint32_t* r, uint32_t a){
    asm volatile("ldmatrix.sync.aligned.m8n8.x4.shared.b16 {%0,%1,%2,%3}, [%4];"
                 : "=r"(r[0]), "=r"(r[1]), "=r"(r[2]), "=r"(r[3]) : "r"(a));
}
__device__ __forceinline__ void ldm_x4t(uint32_t* r, uint32_t a){
    asm volatile("ldmatrix.sync.aligned.m8n8.x4.trans.shared.b16 {%0,%1,%2,%3}, [%4];"
                 : "=r"(r[0]), "=r"(r[1]), "=r"(r[2]), "=r"(r[3]) : "r"(a));
}
__device__ __forceinline__ void ldm_x2t(uint32_t* r, uint32_t a){
    asm volatile("ldmatrix.sync.aligned.m8n8.x2.trans.shared.b16 {%0,%1}, [%2];"
                 : "=r"(r[0]), "=r"(r[1]) : "r"(a));
}
__device__ __forceinline__ void mma16816(float* d, const uint32_t* a, const uint32_t* b){
    asm volatile("mma.sync.aligned.m16n8k16.row.col.f32.bf16.bf16.f32 "
                 "{%0,%1,%2,%3}, {%4,%5,%6,%7}, {%8,%9}, {%0,%1,%2,%3};"
                 : "+f"(d[0]), "+f"(d[1]), "+f"(d[2]), "+f"(d[3])
                 : "r"(a[0]), "r"(a[1]), "r"(a[2]), "r"(a[3]), "r"(b[0]), "r"(b[1]));
}
__device__ __forceinline__ bf bfc(float x){ return __float2bfloat16(x); }
__device__ __forceinline__ uint32_t pack_bf(float x, float y){
    __nv_bfloat162 h; h.x = __float2bfloat16(x); h.y = __float2bfloat16(y);
    return *reinterpret_cast<uint32_t*>(&h);
}

// ------------------------- merged cast kernel (MLP=4) -------------------------
__global__ void castAll_k(const float* __restrict__ a0, const float* __restrict__ a1,
                          const float* __restrict__ a2, const float* __restrict__ a3,
                          const float* __restrict__ w0, const float* __restrict__ w1,
                          const float* __restrict__ w2, const float* __restrict__ w3,
                          const float* __restrict__ w4,
                          const unsigned char* __restrict__ ttm, const float* __restrict__ clsm,
                          bf* __restrict__ outA, bf* __restrict__ outW,
                          unsigned char* __restrict__ comb)
{
    const int y = blockIdx.y;
    const long long tid = (long long)blockIdx.x * 256 + threadIdx.x;
    if (y == 9){
        uchar4 tm[4]; float4 cl[4];
        #pragma unroll
        for (int u = 0; u < 4; ++u){
            long long e = (tid + (long long)u * 131072) * 4;
            tm[u] = *(const uchar4*)(ttm + e);
            cl[u] = *(const float4*)(clsm + (e & 0xFFFFF));
        }
        #pragma unroll
        for (int u = 0; u < 4; ++u){
            long long e = (tid + (long long)u * 131072) * 4;
            uchar4 o;
            o.x = (tm[u].x ? 1 : 0) | (cl[u].x != 0.f ? 2 : 0);
            o.y = (tm[u].y ? 1 : 0) | (cl[u].y != 0.f ? 2 : 0);
            o.z = (tm[u].z ? 1 : 0) | (cl[u].z != 0.f ? 2 : 0);
            o.w = (tm[u].w ? 1 : 0) | (cl[u].w != 0.f ? 2 : 0);
            *(uchar4*)(comb + e) = o;
        }
        return;
    }
    if (y < 4){
        const float* in = (y == 0) ? a0 : (y == 1) ? a1 : (y == 2) ? a2 : a3;
        bf* o = outA + (long long)y * 2097152;
        float4 v[4];
        #pragma unroll
        for (int u = 0; u < 4; ++u)
            v[u] = *(const float4*)(in + (tid + (long long)u * 131072) * 4);
        #pragma unroll
        for (int u = 0; u < 4; ++u){
            long long e = (tid + (long long)u * 131072) * 4;
            __nv_bfloat162 p, q;
            p.x = bfc(v[u].x); p.y = bfc(v[u].y); q.x = bfc(v[u].z); q.y = bfc(v[u].w);
            *(__nv_bfloat162*)(o + e)     = p;
            *(__nv_bfloat162*)(o + e + 2) = q;
        }
    } else {
        int yw = y - 4;
        const float* in = (yw == 0) ? w0 : (yw == 1) ? w1 : (yw == 2) ? w2 : (yw == 3) ? w3 : w4;
        bf* o = outW + (long long)yw * 1048576;
        float4 v[2];
        #pragma unroll
        for (int u = 0; u < 2; ++u)
            v[u] = *(const float4*)(in + (tid + (long long)u * 131072) * 4);
        #pragma unroll
        for (int u = 0; u < 2; ++u){
            long long e = (tid + (long long)u * 131072) * 4;
            __nv_bfloat162 p, q;
            p.x = bfc(v[u].x); p.y = bfc(v[u].y); q.x = bfc(v[u].z); q.y = bfc(v[u].w);
            *(__nv_bfloat162*)(o + e)     = p;
            *(__nv_bfloat162*)(o + e + 2) = q;
        }
    }
}

// ------------------------- generic bf16 GEMM (proj / outproj) ------------------
template<int BN, int NT_, int EPI>
__global__ __launch_bounds__(256, 2)
void tg(const bf* __restrict__ A, const bf* __restrict__ B,
        const float* __restrict__ bias, const float* __restrict__ bias2,
        float* __restrict__ Cf, bf* __restrict__ Cb,
        int K, int lda, int ldb, int ldc)
{
    constexpr int NS = 4;
    constexpr int ASZ = 128 * 40;
    constexpr int BSTR = BN + 8;
    constexpr int BSZ = 32 * BSTR;
    extern __shared__ __align__(16) bf dyn[];
    bf* Asm = dyn;
    bf* Bsm = dyn + NS * ASZ;

    const int m0 = blockIdx.y * 128;
    int n0 = blockIdx.x * BN;
    const int z = blockIdx.z;
    int zi = 0;
    if (EPI == 6){ zi = z; A += (long long)zi * 2048 * 1024; B += (long long)zi * 1024 * 1024; }

    const int t = threadIdx.x, lane = t & 31, warp = t >> 5, wm = warp >> 2, wn = warp & 3;

    float acc[4][NT_][4];
    #pragma unroll
    for (int a = 0; a < 4; ++a)
        #pragma unroll
        for (int b = 0; b < NT_; ++b)
            #pragma unroll
            for (int c = 0; c < 4; ++c) acc[a][b][c] = 0.f;

    auto loadA = [&](int s, int k0){
        #pragma unroll
        for (int q = 0; q < 2; ++q){
            int c = t * 2 + q, row = c >> 2, seg = c & 3;
            cp16(cvta_s(Asm + s * ASZ + row * 40 + seg * 8),
                 A + (long long)(m0 + row) * lda + k0 + seg * 8);
        }
    };
    auto loadB = [&](int s, int k0){
        constexpr int CPR = BN / 8;
        #pragma unroll
        for (int q = 0; q < (32 * CPR) / 256; ++q){
            int c = t * ((32 * CPR) / 256) + q, row = c / CPR, seg = c % CPR;
            cp16(cvta_s(Bsm + s * BSZ + row * BSTR + seg * 8),
                 B + (long long)(k0 + row) * ldb + n0 + seg * 8);
        }
    };

    const int KT = K / 32;
    loadA(0, 0); loadB(0, 0);
    asm volatile("cp.async.commit_group;");
    if (KT > 1){ loadA(1, 32); loadB(1, 32); }
    asm volatile("cp.async.commit_group;");
    if (KT > 2){ loadA(2, 64); loadB(2, 64); }
    asm volatile("cp.async.commit_group;");

    for (int kt = 0; kt < KT; ++kt){
        asm volatile("cp.async.wait_group 2;");
        __syncthreads();
        int kn = kt + 3;
        if (kn < KT){ loadA(kn & 3, kn * 32); loadB(kn & 3, kn * 32); }
        asm volatile("cp.async.commit_group;");

        const int s = kt & 3;
        const uint32_t aBase = cvta_s(Asm + s * ASZ) + ((wm * 64 + (lane & 15)) * 40) * 2;
        const uint32_t bBase = cvta_s(Bsm + s * BSZ);
        #pragma unroll
        for (int ks = 0; ks < 32; ks += 16){
            uint32_t af[4][4], bfrg[NT_][2];
            #pragma unroll
            for (int mt = 0; mt < 4; ++mt)
                ldm_x4(af[mt], aBase + (mt * 16 * 40 + ks + (lane >> 4) * 8) * 2);
            #pragma unroll
            for (int nt = 0; nt < NT_; ++nt)
                ldm_x2t(bfrg[nt], bBase + (((ks + (lane & 15)) * BSTR + wn * (BN / 4) + nt * 8)) * 2);
            #pragma unroll
            for (int mt = 0; mt < 4; ++mt)
                #pragma unroll
                for (int nt = 0; nt < NT_; ++nt) mma16816(acc[mt][nt], af[mt], bfrg[nt]);
        }
    }

    #pragma unroll
    for (int mt = 0; mt < 4; ++mt)
      #pragma unroll
      for (int r2 = 0; r2 < 2; ++r2){
        const int i = m0 + wm * 64 + mt * 16 + (lane >> 2) + r2 * 8;
        #pragma unroll
        for (int nt = 0; nt < NT_; ++nt)
          #pragma unroll
          for (int c2 = 0; c2 < 2; ++c2){
            const int j = n0 + wn * (BN / 4) + nt * 8 + ((lane & 3) << 1) + c2;
            float v = acc[mt][nt][r2 * 2 + c2];
            if (EPI == 6){
                if (zi == 0) v *= SCALE;
                else if (zi == 1) v += bias[j];
                else if (zi == 2) v += bias2[j];
                Cb[(long long)zi * 2048 * 1024 + (long long)i * 1024 + j] = bfc(v);
            } else { // EPI 4
                Cf[(long long)i * ldc + j] = v + bias[j];
            }
          }
      }
}

// ------------------------- fused flash attention kernel ----------------------
// 2 CTAs/SM: single-buffered KV, qs/Pcb overlapped, two-half score processing.
__global__ __launch_bounds__(256, 2)
void fattn_k(const bf* __restrict__ q16, const bf* __restrict__ k16,
             const bf* __restrict__ v16, const bf* __restrict__ rh16,
             const float* __restrict__ rwkm, const float* __restrict__ rrt,
             const float* __restrict__ ttd, const unsigned char* __restrict__ comb,
             bf* __restrict__ av16)
{
    extern __shared__ __align__(16) bf dyn[];
    bf* ks  = dyn;             // 9216 (single buffer)
    bf* vs  = dyn + 9216;      // 9216 (single buffer)
    bf* rhs = dyn + 18432;     // 256*72 ring
    bf* qs  = dyn + 36864;     // 9216, prologue only
    bf* Pcb = dyn + 36864;     // 128*PSTRB, overlaps qs (valid after afq hoist)

    const int i0 = blockIdx.x * 128;
    const int z  = blockIdx.y, bb = z >> 4, nn = z & 15;
    const int t = threadIdx.x, lane = t & 31, w = t >> 5;
    bf* Pw = Pcb + w * 16 * PSTRB;
    const int tbase = 896 - i0;

    const bf* qg = q16 + ((long long)(bb * 1024 + i0)) * 1024 + nn * 64;

    auto loadKV = [&](int j0){
        const bf* kg = k16 + ((long long)(bb * 1024 + j0)) * 1024 + nn * 64;
        const bf* vg = v16 + ((long long)(bb * 1024 + j0)) * 1024 + nn * 64;
        #pragma unroll
        for (int qq = 0; qq < 4; ++qq){
            int c = qq * 256 + t, row = c >> 3, seg = c & 7;
            cp16(cvta_s(ks + row * 72 + seg * 8), kg + (long long)row * 1024 + seg * 8);
        }
        #pragma unroll
        for (int qq = 0; qq < 4; ++qq){
            int c = qq * 256 + t, row = c >> 3, seg = c & 7;
            cp16(cvta_s(vs + row * 72 + seg * 8), vg + (long long)row * 1024 + seg * 8);
        }
    };
    auto loadRH128 = [&](int t0){
        #pragma unroll
        for (int qq = 0; qq < 4; ++qq){
            int c = qq * 256 + t, row = c >> 3, seg = c & 7;
            int tr = t0 + row;
            cp16(cvta_s(rhs + (tr & 255) * 72 + seg * 8),
                 rh16 + (long long)tr * 1024 + nn * 64 + seg * 8);
        }
    };

    // prologue
    #pragma unroll
    for (int qq = 0; qq < 4; ++qq){
        int c = qq * 256 + t, row = c >> 3, seg = c & 7;
        cp16(cvta_s(qs + row * 72 + seg * 8), qg + (long long)row * 1024 + seg * 8);
    }
    loadKV(0);
    loadRH128(tbase);
    loadRH128(tbase + 128);
    asm volatile("cp.async.commit_group;");
    asm volatile("cp.async.wait_group 0;");
    __syncthreads();

    const uint32_t aBase = cvta_s(qs) + ((w * 16 + (lane & 15)) * 72 + (lane >> 4) * 8) * 2;
    const uint32_t rBase = cvta_s(rhs);
    const uint32_t kBase = cvta_s(ks);
    const uint32_t vBase = cvta_s(vs);

    uint32_t afq[4][4];
    #pragma unroll
    for (int s = 0; s < 4; ++s) ldm_x4(afq[s], aBase + (s * 16) * 2);
    __syncthreads();    // all warps done reading qs before Pcb (overlapping) writes

    float accO[8][4];
    #pragma unroll
    for (int a = 0; a < 8; ++a){ accO[a][0] = 0.f; accO[a][1] = 0.f; accO[a][2] = 0.f; accO[a][3] = 0.f; }
    float lsumA = 0.f, lsumB = 0.f;

    const int rl0 = lane >> 2;
    const int iA = i0 + w * 16 + rl0, iB = iA + 8;
    const long long tba = ((long long)(bb * 1024 + iA) * 16 + nn) * 2;
    const long long tbb = ((long long)(bb * 1024 + iB) * 16 + nn) * 2;
    const float tdA0 = ttd[tba], tdA1 = ttd[tba + 1];
    const float tdB0 = ttd[tbb], tdB1 = ttd[tbb + 1];
    const int nt0 = 14 - 2 * w;
    const int bnOff = (lane & 7) + ((lane >> 4) << 3);
    const int bkOff = ((lane >> 3) & 1) << 3;

    for (int jt = 0; jt < 8; ++jt){
        const int j0 = jt * 128;
        const int tb0 = tbase + j0;
        const float* rrtp = rrt + nn * Rc + tb0;

        // ---- band-limited pos mma over ring (18 tiles, 3 groups of 6) ----
        #pragma unroll
        for (int g = 0; g < 3; ++g){
            float accP[6][4];
            #pragma unroll
            for (int a = 0; a < 6; ++a){ accP[a][0]=0.f; accP[a][1]=0.f; accP[a][2]=0.f; accP[a][3]=0.f; }
            #pragma unroll
            for (int s = 0; s < 4; ++s){
                #pragma unroll
                for (int u = 0; u < 3; ++u){
                    int ntp = nt0 + g * 6 + u * 2;
                    uint32_t b4[4];
                    ldm_x4(b4, rBase + (((unsigned)(tb0 + ntp * 8 + bnOff) & 255u) * 72 + s * 16 + bkOff) * 2);
                    mma16816(accP[2 * u],     afq[s], b4);
                    mma16816(accP[2 * u + 1], afq[s], b4 + 2);
                }
            }
            #pragma unroll
            for (int u = 0; u < 6; ++u){
                int nt = nt0 + g * 6 + u;
                #pragma unroll
                for (int c = 0; c < 4; ++c){
                    int rl = rl0 + ((c >> 1) << 3);
                    int di = w * 16 + rl;
                    int ct = nt * 8 + ((lane & 3) << 1) + (c & 1);
                    int dj = ct - 128 + di;
                    if (dj >= 0 && dj < 128)
                        Pw[rl * PSTRB + dj] = bfc(accP[u][c] + rrtp[ct]);
                }
            }
        }
        __syncthreads();     // all ring reads done
        if (jt < 7){
            loadRH128(tb0 + 256);
            asm volatile("cp.async.commit_group;");
        }

        const float* rwp = rwkm + (long long)z * 1024 + j0;
        const unsigned char* cmA = comb + (long long)(bb * 1024 + iA) * 1024 + j0;
        const unsigned char* cmB = comb + (long long)(bb * 1024 + iB) * 1024 + j0;

        // ---- two 64-col halves: content mma -> exp/pack -> PV mma ----
        #pragma unroll
        for (int hf = 0; hf < 2; ++hf){
            float accC[8][4];
            #pragma unroll
            for (int a = 0; a < 8; ++a){ accC[a][0]=0.f; accC[a][1]=0.f; accC[a][2]=0.f; accC[a][3]=0.f; }
            #pragma unroll
            for (int s = 0; s < 4; ++s){
                #pragma unroll
                for (int npl = 0; npl < 4; ++npl){
                    int np = hf * 4 + npl;
                    uint32_t b4[4];
                    ldm_x4(b4, kBase + ((np * 16 + bnOff) * 72 + s * 16 + bkOff) * 2);
                    mma16816(accC[2 * npl],     afq[s], b4);
                    mma16816(accC[2 * npl + 1], afq[s], b4 + 2);
                }
            }

            uint32_t pkA[8], pkB[8];
            #pragma unroll
            for (int nt = 0; nt < 8; ++nt){
                const int djp = hf * 64 + nt * 8 + ((lane & 3) << 1);
                float2 rw = *(const float2*)(rwp + djp);
                {
                    uchar2 cm = *(const uchar2*)(cmA + djp);
                    __nv_bfloat162 pb = *(const __nv_bfloat162*)(&Pw[rl0 * PSTRB + djp]);
                    float clx = (cm.x & 2) ? 1.f : 0.f, cly = (cm.y & 2) ? 1.f : 0.f;
                    float t0 = (cm.x & 1) ? tdA1 : tdA0, t1 = (cm.y & 1) ? tdA1 : tdA0;
                    float e0 = __expf(accC[nt][0] + rw.x + (__bfloat162float(pb.x) + t0) * clx);
                    float e1 = __expf(accC[nt][1] + rw.y + (__bfloat162float(pb.y) + t1) * cly);
                    lsumA += e0 + e1;
                    pkA[nt] = pack_bf(e0, e1);
                }
                {
                    uchar2 cm = *(const uchar2*)(cmB + djp);
                    __nv_bfloat162 pb = *(const __nv_bfloat162*)(&Pw[(rl0 + 8) * PSTRB + djp]);
                    float clx = (cm.x & 2) ? 1.f : 0.f, cly = (cm.y & 2) ? 1.f : 0.f;
                    float t0 = (cm.x & 1) ? tdB1 : tdB0, t1 = (cm.y & 1) ? tdB1 : tdB0;
                    float e0 = __expf(accC[nt][2] + rw.x + (__bfloat162float(pb.x) + t0) * clx);
                    float e1 = __expf(accC[nt][3] + rw.y + (__bfloat162float(pb.y) + t1) * cly);
                    lsumB += e0 + e1;
                    pkB[nt] = pack_bf(e0, e1);
                }
            }

            #pragma unroll
            for (int u = 0; u < 4; ++u){
                const int kb = hf * 4 + u;
                uint32_t pf[4];
                pf[0] = pkA[2 * u];     pf[1] = pkB[2 * u];
                pf[2] = pkA[2 * u + 1]; pf[3] = pkB[2 * u + 1];
                #pragma unroll
                for (int np = 0; np < 4; ++np){
                    uint32_t b4[4];
                    ldm_x4t(b4, vBase + ((kb * 16 + (lane & 15)) * 72 + np * 16 + (lane >> 4) * 8) * 2);
                    mma16816(accO[2 * np],     pf, b4);
                    mma16816(accO[2 * np + 1], pf, b4 + 2);
                }
            }
        }

        __syncthreads();     // all ks/vs reads done
        if (jt < 7){
            loadKV(j0 + 128);
            asm volatile("cp.async.commit_group;");
            asm volatile("cp.async.wait_group 0;");
            __syncthreads(); // ring + KV data visible to all warps
        }
    }

    // ---- finalize ----
    lsumA += __shfl_xor_sync(0xffffffffu, lsumA, 1);
    lsumA += __shfl_xor_sync(0xffffffffu, lsumA, 2);
    lsumB += __shfl_xor_sync(0xffffffffu, lsumB, 1);
    lsumB += __shfl_xor_sync(0xffffffffu, lsumB, 2);
    float invA = 1.0f / lsumA, invB = 1.0f / lsumB;
    int rA = bb * 1024 + iA, rB = bb * 1024 + iB;
    #pragma unroll
    for (int nt = 0; nt < 8; ++nt){
        int col = nn * 64 + nt * 8 + ((lane & 3) << 1);
        __nv_bfloat162 p0, p1;
        p0.x = bfc(accO[nt][0] * invA); p0.y = bfc(accO[nt][1] * invA);
        p1.x = bfc(accO[nt][2] * invB); p1.y = bfc(accO[nt][3] * invB);
        *(__nv_bfloat162*)(av16 + (long long)rA * 1024 + col) = p0;
        *(__nv_bfloat162*)(av16 + (long long)rB * 1024 + col) = p1;
    }
}

// ------------------------- merged dot kernels (vectorized loads) ---------------
__global__ void dots_k(const bf* __restrict__ q16, const bf* __restrict__ k16,
                       const bf* __restrict__ rh16,
                       const float* __restrict__ rwb, const float* __restrict__ rrb,
                       const float* __restrict__ rsb, const float* __restrict__ seg,
                       const int* __restrict__ amask,
                       float* __restrict__ rwkm, float* __restrict__ rrt, float* __restrict__ ttd)
{
    int gw = (blockIdx.x * blockDim.x + threadIdx.x) >> 5;
    int lane = threadIdx.x & 31;
    if (blockIdx.y == 0){
        int zz = gw >> 10, j = gw & (Sc - 1);
        int b = zz >> 4, n = zz & 15;
        const bf* kp = k16 + ((long long)(b * 1024 + j)) * 1024 + n * 64;
        __nv_bfloat162 kk = ((const __nv_bfloat162*)kp)[lane];
        float2 rw = *(const float2*)(rwb + n * Hc + 2 * lane);
        float d = rw.x * __bfloat162float(kk.x) + rw.y * __bfloat162float(kk.y);
        #pragma unroll
        for (int o = 16; o; o >>= 1) d += __shfl_down_sync(0xffffffffu, d, o);
        if (lane == 0)
            rwkm[gw] = d * SCALE - INFV * (1.0f - (float)amask[b * Sc + j]);
    } else if (blockIdx.y == 1){
        int n = gw >> 11, tt2 = gw & (Rc - 1);
        const bf* rp = rh16 + (long long)tt2 * 1024 + n * 64;
        __nv_bfloat162 rr = ((const __nv_bfloat162*)rp)[lane];
        float2 rb = *(const float2*)(rrb + n * Hc + 2 * lane);
        float d = rb.x * __bfloat162float(rr.x) + rb.y * __bfloat162float(rr.y);
        #pragma unroll
        for (int o = 16; o; o >>= 1) d += __shfl_down_sync(0xffffffffu, d, o);
        if (lane == 0) rrt[gw] = d * SCALE;
    } else {
        int n = gw & 15;
        long long bi = gw >> 4;
        const bf* qp = q16 + bi * 1024 + n * 64;
        __nv_bfloat162 qq = ((const __nv_bfloat162*)qp)[lane];
        float2 e0v = *(const float2*)(seg + n * Hc + 2 * lane);
        float2 e1v = *(const float2*)(seg + Nc * Hc + n * Hc + 2 * lane);
        float2 rv  = *(const float2*)(rsb + n * Hc + 2 * lane);
        float qx = __bfloat162float(qq.x), qy = __bfloat162float(qq.y);
        float d0 = qx * e0v.x + qy * e0v.y;
        float d1 = qx * e1v.x + qy * e1v.y;
        float s0 = rv.x * e0v.x + rv.y * e0v.y;
        float s1 = rv.x * e1v.x + rv.y * e1v.y;
        #pragma unroll
        for (int o = 16; o; o >>= 1){
            d0 += __shfl_down_sync(0xffffffffu, d0, o);
            d1 += __shfl_down_sync(0xffffffffu, d1, o);
            s0 += __shfl_down_sync(0xffffffffu, s0, o);
            s1 += __shfl_down_sync(0xffffffffu, s1, o);
        }
        if (lane == 0){
            ttd[2 * gw]     = d0 + SCALE * s0;
            ttd[2 * gw + 1] = d1 + SCALE * s1;
        }
    }
}

// ------------------------- residual + LayerNorm -------------------------
__global__ void ln_k(const float* __restrict__ query, const float* __restrict__ ao,
                     const float* __restrict__ gamma, const float* __restrict__ beta,
                     float* __restrict__ out){
    __shared__ float red[256];
    long long base = (long long)blockIdx.x * Dc;
    int t = threadIdx.x;
    float x[4]; float s = 0.f;
    #pragma unroll
    for (int u = 0; u < 4; ++u){ x[u] = query[base + t + u * 256] + ao[base + t + u * 256]; s += x[u]; }
    red[t] = s; __syncthreads();
    #pragma unroll
    for (int o = 128; o; o >>= 1){ if (t < o) red[t] += red[t + o]; __syncthreads(); }
    float mu = red[0] * (1.0f / Dc); __syncthreads();
    float s2 = 0.f;
    #pragma unroll
    for (int u = 0; u < 4; ++u){ float d = x[u] - mu; s2 += d * d; }
    red[t] = s2; __syncthreads();
    #pragma unroll
    for (int o = 128; o; o >>= 1){ if (t < o) red[t] += red[t + o]; __syncthreads(); }
    float inv = rsqrtf(red[0] * (1.0f / Dc) + EPSV);
    #pragma unroll
    for (int u = 0; u < 4; ++u){
        int c = t + u * 256;
        out[base + c] = (x[u] - mu) * inv * gamma[c] + beta[c];
    }
}

// ------------------------- driver -------------------------
extern "C" void kernel_launch(void* const* d_in, const int* in_sizes, int n_in,
                              void* d_out, int out_size)
{
    const float* query = (const float*)d_in[0];
    const float* key   = (const float*)d_in[1];
    const float* value = (const float*)d_in[2];
    const float* r     = (const float*)d_in[3];
    const float* clsm  = (const float*)d_in[4];
    const float* Wq    = (const float*)d_in[5];
    const float* Wk    = (const float*)d_in[6];
    const float* bk    = (const float*)d_in[7];
    const float* Wv    = (const float*)d_in[8];
    const float* bv    = (const float*)d_in[9];
    const float* Wo    = (const float*)d_in[10];
    const float* bo    = (const float*)d_in[11];
    const float* rwb   = (const float*)d_in[12];
    const float* rrb   = (const float*)d_in[13];
    const float* rkern = (const float*)d_in[14];
    const float* rsb   = (const float*)d_in[15];
    const float* seg   = (const float*)d_in[16];
    const float* gamma = (const float*)d_in[17];
    const float* beta  = (const float*)d_in[18];
    const unsigned char* ttm = (const unsigned char*)d_in[19];
    const int*   amask = (const int*)d_in[20];
    float* out = (float*)d_out;

    bf *in16, *w16, *proj, *av16;
    float *ao, *rwk, *rrt, *ttd;
    unsigned char* comb;
    cudaGetSymbolAddress((void**)&in16, g_in16);
    cudaGetSymbolAddress((void**)&w16,  g_w16);
    cudaGetSymbolAddress((void**)&proj, g_proj);
    cudaGetSymbolAddress((void**)&av16, g_av16);
    cudaGetSymbolAddress((void**)&ao,   g_ao);
    cudaGetSymbolAddress((void**)&rwk,  g_rwk);
    cudaGetSymbolAddress((void**)&rrt,  g_rrt);
    cudaGetSymbolAddress((void**)&ttd,  g_ttd);
    cudaGetSymbolAddress((void**)&comb, g_comb);

    bf* q16  = proj;
    bf* k16  = proj + 1LL * 2048 * 1024;
    bf* v16  = proj + 2LL * 2048 * 1024;
    bf* rh16 = proj + 3LL * 2048 * 1024;

    auto k6 = tg<128, 4, 6>;
    auto k4 = tg<128, 4, 4>;
    cudaFuncSetAttribute(k6, cudaFuncAttributeMaxDynamicSharedMemorySize, 75776);
    cudaFuncSetAttribute(k4, cudaFuncAttributeMaxDynamicSharedMemorySize, 75776);
    cudaFuncSetAttribute(fattn_k, cudaFuncAttributeMaxDynamicSharedMemorySize, 108544);

    // 0) casts + comb (merged, MLP=4)
    castAll_k<<<dim3(512, 10), 256>>>(query, key, value, r, Wq, Wk, Wv, rkern, Wo,
                                      ttm, clsm, in16, w16, comb);

    // 1) merged projections
    k6<<<dim3(8, 16, 4), 256, 75776>>>(in16, w16, bk, bv, nullptr, proj,
        1024, 1024, 1024, 0);

    // 2) merged bias-dot tables (mask folded into rwk)
    dots_k<<<dim3(4096, 3), 256>>>(q16, k16, rh16, rwb, rrb, rsb, seg, amask, rwk, rrt, ttd);

    // 3) fused scores + softmax + PV (2 CTAs/SM)
    fattn_k<<<dim3(8, 32), 256, 108544>>>(q16, k16, v16, rh16,
        rwk, rrt, ttd, comb, av16);

    // 4) output projection + bias
    k4<<<dim3(8, 16, 1), 256, 75776>>>(av16, w16 + 4LL * 1024 * 1024, bo, nullptr, ao, nullptr,
        1024, 1024, 1024, 1024);

    // 5) residual + LayerNorm
    ln_k<<<Bc * Sc, 256>>>(query, ao, gamma, beta, out);

    (void)in_sizes; (void)n_in; (void)out_size;
}

// round 16
// speedup vs baseline: 1.1224x; 1.0185x over previous
#include <cuda_runtime.h>
#include <cuda_bf16.h>
#include <math.h>
#include <stdint.h>

#define Bc 2
#define Sc 1024
#define Dc 1024
#define Nc 16
#define Hc 64
#define NHc 1024
#define Rc 2048
#define SCALE 0.125f
#define INFV 1000000.0f
#define EPSV 1e-9f
#define PSTRB 136

typedef __nv_bfloat16 bf;

// ------------------------- scratch -------------------------
__device__ bf g_in16[4 * 2048 * 1024];
__device__ bf g_w16 [5 * 1024 * 1024];
__device__ bf g_proj[4 * 2048 * 1024];
__device__ bf g_av16[2048 * 1024];
__device__ float g_ao[2048 * 1024];
__device__ float g_rwk[32 * 1024];
__device__ float g_rrt[16 * 2048];
__device__ float g_ttd[2048 * 16 * 2];
__device__ unsigned char g_comb[2 * 1024 * 1024];

// ------------------------- helpers -------------------------
__device__ __forceinline__ uint32_t cvta_s(const void* p){ return (uint32_t)__cvta_generic_to_shared(p); }
__device__ __forceinline__ void cp16(uint32_t d, const void* s){
    asm volatile("cp.async.cg.shared.global [%0], [%1], 16;" :: "r"(d), "l"(s));
}
__device__ __forceinline__ void ldm_x4(uint32_t* r, uint32_t a){
    asm volatile("ldmatrix.sync.aligned.m8n8.x4.shared.b16 {%0,%1,%2,%3}, [%4];"
                 : "=r"(r[0]), "=r"(r[1]), "=r"(r[2]), "=r"(r[3]) : "r"(a));
}
__device__ __forceinline__ void ldm_x4t(uint32_t* r, uint32_t a){
    asm volatile("ldmatrix.sync.aligned.m8n8.x4.trans.shared.b16 {%0,%1,%2,%3}, [%4];"
                 : "=r"(r[0]), "=r"(r[1]), "=r"(r[2]), "=r"(r[3]) : "r"(a));
}
__device__ __forceinline__ void mma16816(float* d, const uint32_t* a, const uint32_t* b){
    asm volatile("mma.sync.aligned.m16n8k16.row.col.f32.bf16.bf16.f32 "
                 "{%0,%1,%2,%3}, {%4,%5,%6,%7}, {%8,%9}, {%0,%1,%2,%3};"
                 : "+f"(d[0]), "+f"(d[1]), "+f"(d[2]), "+f"(d[3])
                 : "r"(a[0]), "r"(a[1]), "r"(a[2]), "r"(a[3]), "r"(b[0]), "r"(b[1]));
}
__device__ __forceinline__ bf bfc(float x){ return __float2bfloat16(x); }
__device__ __forceinline__ uint32_t pack_bf(float x, float y){
    __nv_bfloat162 h; h.x = __float2bfloat16(x); h.y = __float2bfloat16(y);
    return *reinterpret_cast<uint32_t*>(&h);
}

// ------------------------- merged cast kernel (MLP=8) -------------------------
// grid (256, 10). y 0..3: A inputs (8 f4/thr); 4..8: W (4 f4/thr); 9: comb (8 u4/thr)
__global__ void castAll_k(const float* __restrict__ a0, const float* __restrict__ a1,
                          const float* __restrict__ a2, const float* __restrict__ a3,
                          const float* __restrict__ w0, const float* __restrict__ w1,
                          const float* __restrict__ w2, const float* __restrict__ w3,
                          const float* __restrict__ w4,
                          const unsigned char* __restrict__ ttm, const float* __restrict__ clsm,
                          bf* __restrict__ outA, bf* __restrict__ outW,
                          unsigned char* __restrict__ comb)
{
    const int y = blockIdx.y;
    const long long tid = (long long)blockIdx.x * 256 + threadIdx.x;   // 0..65535
    if (y == 9){
        uchar4 tm[8]; float4 cl[8];
        #pragma unroll
        for (int u = 0; u < 8; ++u){
            long long e = (tid + (long long)u * 65536) * 4;
            tm[u] = *(const uchar4*)(ttm + e);
            cl[u] = *(const float4*)(clsm + (e & 0xFFFFF));
        }
        #pragma unroll
        for (int u = 0; u < 8; ++u){
            long long e = (tid + (long long)u * 65536) * 4;
            uchar4 o;
            o.x = (tm[u].x ? 1 : 0) | (cl[u].x != 0.f ? 2 : 0);
            o.y = (tm[u].y ? 1 : 0) | (cl[u].y != 0.f ? 2 : 0);
            o.z = (tm[u].z ? 1 : 0) | (cl[u].z != 0.f ? 2 : 0);
            o.w = (tm[u].w ? 1 : 0) | (cl[u].w != 0.f ? 2 : 0);
            *(uchar4*)(comb + e) = o;
        }
        return;
    }
    if (y < 4){
        const float* in = (y == 0) ? a0 : (y == 1) ? a1 : (y == 2) ? a2 : a3;
        bf* o = outA + (long long)y * 2097152;
        float4 v[8];
        #pragma unroll
        for (int u = 0; u < 8; ++u)
            v[u] = *(const float4*)(in + (tid + (long long)u * 65536) * 4);
        #pragma unroll
        for (int u = 0; u < 8; ++u){
            long long e = (tid + (long long)u * 65536) * 4;
            __nv_bfloat162 p, q;
            p.x = bfc(v[u].x); p.y = bfc(v[u].y); q.x = bfc(v[u].z); q.y = bfc(v[u].w);
            *(__nv_bfloat162*)(o + e)     = p;
            *(__nv_bfloat162*)(o + e + 2) = q;
        }
    } else {
        int yw = y - 4;
        const float* in = (yw == 0) ? w0 : (yw == 1) ? w1 : (yw == 2) ? w2 : (yw == 3) ? w3 : w4;
        bf* o = outW + (long long)yw * 1048576;
        float4 v[4];
        #pragma unroll
        for (int u = 0; u < 4; ++u)
            v[u] = *(const float4*)(in + (tid + (long long)u * 65536) * 4);
        #pragma unroll
        for (int u = 0; u < 4; ++u){
            long long e = (tid + (long long)u * 65536) * 4;
            __nv_bfloat162 p, q;
            p.x = bfc(v[u].x); p.y = bfc(v[u].y); q.x = bfc(v[u].z); q.y = bfc(v[u].w);
            *(__nv_bfloat162*)(o + e)     = p;
            *(__nv_bfloat162*)(o + e + 2) = q;
        }
    }
}

// ------------------------- generic bf16 GEMM (proj / outproj) ------------------
// B-fragments via ldm.x4.trans (2 n8-tiles per LDSM)
template<int BN, int NT_, int EPI>
__global__ __launch_bounds__(256, 2)
void tg(const bf* __restrict__ A, const bf* __restrict__ B,
        const float* __restrict__ bias, const float* __restrict__ bias2,
        float* __restrict__ Cf, bf* __restrict__ Cb,
        int K, int lda, int ldb, int ldc)
{
    constexpr int NS = 4;
    constexpr int ASZ = 128 * 40;
    constexpr int BSTR = BN + 8;
    constexpr int BSZ = 32 * BSTR;
    extern __shared__ __align__(16) bf dyn[];
    bf* Asm = dyn;
    bf* Bsm = dyn + NS * ASZ;

    const int m0 = blockIdx.y * 128;
    int n0 = blockIdx.x * BN;
    const int z = blockIdx.z;
    int zi = 0;
    if (EPI == 6){ zi = z; A += (long long)zi * 2048 * 1024; B += (long long)zi * 1024 * 1024; }

    const int t = threadIdx.x, lane = t & 31, warp = t >> 5, wm = warp >> 2, wn = warp & 3;

    float acc[4][NT_][4];
    #pragma unroll
    for (int a = 0; a < 4; ++a)
        #pragma unroll
        for (int b = 0; b < NT_; ++b)
            #pragma unroll
            for (int c = 0; c < 4; ++c) acc[a][b][c] = 0.f;

    auto loadA = [&](int s, int k0){
        #pragma unroll
        for (int q = 0; q < 2; ++q){
            int c = t * 2 + q, row = c >> 2, seg = c & 3;
            cp16(cvta_s(Asm + s * ASZ + row * 40 + seg * 8),
                 A + (long long)(m0 + row) * lda + k0 + seg * 8);
        }
    };
    auto loadB = [&](int s, int k0){
        constexpr int CPR = BN / 8;
        #pragma unroll
        for (int q = 0; q < (32 * CPR) / 256; ++q){
            int c = t * ((32 * CPR) / 256) + q, row = c / CPR, seg = c % CPR;
            cp16(cvta_s(Bsm + s * BSZ + row * BSTR + seg * 8),
                 B + (long long)(k0 + row) * ldb + n0 + seg * 8);
        }
    };

    const int KT = K / 32;
    loadA(0, 0); loadB(0, 0);
    asm volatile("cp.async.commit_group;");
    if (KT > 1){ loadA(1, 32); loadB(1, 32); }
    asm volatile("cp.async.commit_group;");
    if (KT > 2){ loadA(2, 64); loadB(2, 64); }
    asm volatile("cp.async.commit_group;");

    for (int kt = 0; kt < KT; ++kt){
        asm volatile("cp.async.wait_group 2;");
        __syncthreads();
        int kn = kt + 3;
        if (kn < KT){ loadA(kn & 3, kn * 32); loadB(kn & 3, kn * 32); }
        asm volatile("cp.async.commit_group;");

        const int s = kt & 3;
        const uint32_t aBase = cvta_s(Asm + s * ASZ) + ((wm * 64 + (lane & 15)) * 40) * 2;
        const uint32_t bBase = cvta_s(Bsm + s * BSZ);
        #pragma unroll
        for (int ks = 0; ks < 32; ks += 16){
            uint32_t af[4][4], bfrg[NT_][2];
            #pragma unroll
            for (int mt = 0; mt < 4; ++mt)
                ldm_x4(af[mt], aBase + (mt * 16 * 40 + ks + (lane >> 4) * 8) * 2);
            #pragma unroll
            for (int npair = 0; npair < NT_ / 2; ++npair){
                uint32_t b4[4];
                ldm_x4t(b4, bBase + (((ks + (lane & 15)) * BSTR + wn * (BN / 4) + npair * 16 + (lane >> 4) * 8)) * 2);
                bfrg[2 * npair][0] = b4[0]; bfrg[2 * npair][1] = b4[1];
                bfrg[2 * npair + 1][0] = b4[2]; bfrg[2 * npair + 1][1] = b4[3];
            }
            #pragma unroll
            for (int mt = 0; mt < 4; ++mt)
                #pragma unroll
                for (int nt = 0; nt < NT_; ++nt) mma16816(acc[mt][nt], af[mt], bfrg[nt]);
        }
    }

    #pragma unroll
    for (int mt = 0; mt < 4; ++mt)
      #pragma unroll
      for (int r2 = 0; r2 < 2; ++r2){
        const int i = m0 + wm * 64 + mt * 16 + (lane >> 2) + r2 * 8;
        #pragma unroll
        for (int nt = 0; nt < NT_; ++nt)
          #pragma unroll
          for (int c2 = 0; c2 < 2; ++c2){
            const int j = n0 + wn * (BN / 4) + nt * 8 + ((lane & 3) << 1) + c2;
            float v = acc[mt][nt][r2 * 2 + c2];
            if (EPI == 6){
                if (zi == 0) v *= SCALE;
                else if (zi == 1) v += bias[j];
                else if (zi == 2) v += bias2[j];
                Cb[(long long)zi * 2048 * 1024 + (long long)i * 1024 + j] = bfc(v);
            } else { // EPI 4
                Cf[(long long)i * ldc + j] = v + bias[j];
            }
          }
      }
}

// ------------------------- fused flash attention kernel (R15 frozen) ----------
__global__ __launch_bounds__(256, 2)
void fattn_k(const bf* __restrict__ q16, const bf* __restrict__ k16,
             const bf* __restrict__ v16, const bf* __restrict__ rh16,
             const float* __restrict__ rwkm, const float* __restrict__ rrt,
             const float* __restrict__ ttd, const unsigned char* __restrict__ comb,
             bf* __restrict__ av16)
{
    extern __shared__ __align__(16) bf dyn[];
    bf* ks  = dyn;
    bf* vs  = dyn + 9216;
    bf* rhs = dyn + 18432;
    bf* qs  = dyn + 36864;
    bf* Pcb = dyn + 36864;

    const int i0 = blockIdx.x * 128;
    const int z  = blockIdx.y, bb = z >> 4, nn = z & 15;
    const int t = threadIdx.x, lane = t & 31, w = t >> 5;
    bf* Pw = Pcb + w * 16 * PSTRB;
    const int tbase = 896 - i0;

    const bf* qg = q16 + ((long long)(bb * 1024 + i0)) * 1024 + nn * 64;

    auto loadKV = [&](int j0){
        const bf* kg = k16 + ((long long)(bb * 1024 + j0)) * 1024 + nn * 64;
        const bf* vg = v16 + ((long long)(bb * 1024 + j0)) * 1024 + nn * 64;
        #pragma unroll
        for (int qq = 0; qq < 4; ++qq){
            int c = qq * 256 + t, row = c >> 3, seg = c & 7;
            cp16(cvta_s(ks + row * 72 + seg * 8), kg + (long long)row * 1024 + seg * 8);
        }
        #pragma unroll
        for (int qq = 0; qq < 4; ++qq){
            int c = qq * 256 + t, row = c >> 3, seg = c & 7;
            cp16(cvta_s(vs + row * 72 + seg * 8), vg + (long long)row * 1024 + seg * 8);
        }
    };
    auto loadRH128 = [&](int t0){
        #pragma unroll
        for (int qq = 0; qq < 4; ++qq){
            int c = qq * 256 + t, row = c >> 3, seg = c & 7;
            int tr = t0 + row;
            cp16(cvta_s(rhs + (tr & 255) * 72 + seg * 8),
                 rh16 + (long long)tr * 1024 + nn * 64 + seg * 8);
        }
    };

    #pragma unroll
    for (int qq = 0; qq < 4; ++qq){
        int c = qq * 256 + t, row = c >> 3, seg = c & 7;
        cp16(cvta_s(qs + row * 72 + seg * 8), qg + (long long)row * 1024 + seg * 8);
    }
    loadKV(0);
    loadRH128(tbase);
    loadRH128(tbase + 128);
    asm volatile("cp.async.commit_group;");
    asm volatile("cp.async.wait_group 0;");
    __syncthreads();

    const uint32_t aBase = cvta_s(qs) + ((w * 16 + (lane & 15)) * 72 + (lane >> 4) * 8) * 2;
    const uint32_t rBase = cvta_s(rhs);
    const uint32_t kBase = cvta_s(ks);
    const uint32_t vBase = cvta_s(vs);

    uint32_t afq[4][4];
    #pragma unroll
    for (int s = 0; s < 4; ++s) ldm_x4(afq[s], aBase + (s * 16) * 2);
    __syncthreads();

    float accO[8][4];
    #pragma unroll
    for (int a = 0; a < 8; ++a){ accO[a][0] = 0.f; accO[a][1] = 0.f; accO[a][2] = 0.f; accO[a][3] = 0.f; }
    float lsumA = 0.f, lsumB = 0.f;

    const int rl0 = lane >> 2;
    const int iA = i0 + w * 16 + rl0, iB = iA + 8;
    const long long tba = ((long long)(bb * 1024 + iA) * 16 + nn) * 2;
    const long long tbb = ((long long)(bb * 1024 + iB) * 16 + nn) * 2;
    const float tdA0 = ttd[tba], tdA1 = ttd[tba + 1];
    const float tdB0 = ttd[tbb], tdB1 = ttd[tbb + 1];
    const int nt0 = 14 - 2 * w;
    const int bnOff = (lane & 7) + ((lane >> 4) << 3);
    const int bkOff = ((lane >> 3) & 1) << 3;

    for (int jt = 0; jt < 8; ++jt){
        const int j0 = jt * 128;
        const int tb0 = tbase + j0;
        const float* rrtp = rrt + nn * Rc + tb0;

        #pragma unroll
        for (int g = 0; g < 3; ++g){
            float accP[6][4];
            #pragma unroll
            for (int a = 0; a < 6; ++a){ accP[a][0]=0.f; accP[a][1]=0.f; accP[a][2]=0.f; accP[a][3]=0.f; }
            #pragma unroll
            for (int s = 0; s < 4; ++s){
                #pragma unroll
                for (int u = 0; u < 3; ++u){
                    int ntp = nt0 + g * 6 + u * 2;
                    uint32_t b4[4];
                    ldm_x4(b4, rBase + (((unsigned)(tb0 + ntp * 8 + bnOff) & 255u) * 72 + s * 16 + bkOff) * 2);
                    mma16816(accP[2 * u],     afq[s], b4);
                    mma16816(accP[2 * u + 1], afq[s], b4 + 2);
                }
            }
            #pragma unroll
            for (int u = 0; u < 6; ++u){
                int nt = nt0 + g * 6 + u;
                #pragma unroll
                for (int c = 0; c < 4; ++c){
                    int rl = rl0 + ((c >> 1) << 3);
                    int di = w * 16 + rl;
                    int ct = nt * 8 + ((lane & 3) << 1) + (c & 1);
                    int dj = ct - 128 + di;
                    if (dj >= 0 && dj < 128)
                        Pw[rl * PSTRB + dj] = bfc(accP[u][c] + rrtp[ct]);
                }
            }
        }
        __syncthreads();
        if (jt < 7){
            loadRH128(tb0 + 256);
            asm volatile("cp.async.commit_group;");
        }

        const float* rwp = rwkm + (long long)z * 1024 + j0;
        const unsigned char* cmA = comb + (long long)(bb * 1024 + iA) * 1024 + j0;
        const unsigned char* cmB = comb + (long long)(bb * 1024 + iB) * 1024 + j0;

        #pragma unroll
        for (int hf = 0; hf < 2; ++hf){
            float accC[8][4];
            #pragma unroll
            for (int a = 0; a < 8; ++a){ accC[a][0]=0.f; accC[a][1]=0.f; accC[a][2]=0.f; accC[a][3]=0.f; }
            #pragma unroll
            for (int s = 0; s < 4; ++s){
                #pragma unroll
                for (int npl = 0; npl < 4; ++npl){
                    int np = hf * 4 + npl;
                    uint32_t b4[4];
                    ldm_x4(b4, kBase + ((np * 16 + bnOff) * 72 + s * 16 + bkOff) * 2);
                    mma16816(accC[2 * npl],     afq[s], b4);
                    mma16816(accC[2 * npl + 1], afq[s], b4 + 2);
                }
            }

            uint32_t pkA[8], pkB[8];
            #pragma unroll
            for (int nt = 0; nt < 8; ++nt){
                const int djp = hf * 64 + nt * 8 + ((lane & 3) << 1);
                float2 rw = *(const float2*)(rwp + djp);
                {
                    uchar2 cm = *(const uchar2*)(cmA + djp);
                    __nv_bfloat162 pb = *(const __nv_bfloat162*)(&Pw[rl0 * PSTRB + djp]);
                    float clx = (cm.x & 2) ? 1.f : 0.f, cly = (cm.y & 2) ? 1.f : 0.f;
                    float t0 = (cm.x & 1) ? tdA1 : tdA0, t1 = (cm.y & 1) ? tdA1 : tdA0;
                    float e0 = __expf(accC[nt][0] + rw.x + (__bfloat162float(pb.x) + t0) * clx);
                    float e1 = __expf(accC[nt][1] + rw.y + (__bfloat162float(pb.y) + t1) * cly);
                    lsumA += e0 + e1;
                    pkA[nt] = pack_bf(e0, e1);
                }
                {
                    uchar2 cm = *(const uchar2*)(cmB + djp);
                    __nv_bfloat162 pb = *(const __nv_bfloat162*)(&Pw[(rl0 + 8) * PSTRB + djp]);
                    float clx = (cm.x & 2) ? 1.f : 0.f, cly = (cm.y & 2) ? 1.f : 0.f;
                    float t0 = (cm.x & 1) ? tdB1 : tdB0, t1 = (cm.y & 1) ? tdB1 : tdB0;
                    float e0 = __expf(accC[nt][2] + rw.x + (__bfloat162float(pb.x) + t0) * clx);
                    float e1 = __expf(accC[nt][3] + rw.y + (__bfloat162float(pb.y) + t1) * cly);
                    lsumB += e0 + e1;
                    pkB[nt] = pack_bf(e0, e1);
                }
            }

            #pragma unroll
            for (int u = 0; u < 4; ++u){
                const int kb = hf * 4 + u;
                uint32_t pf[4];
                pf[0] = pkA[2 * u];     pf[1] = pkB[2 * u];
                pf[2] = pkA[2 * u + 1]; pf[3] = pkB[2 * u + 1];
                #pragma unroll
                for (int np = 0; np < 4; ++np){
                    uint32_t b4[4];
                    ldm_x4t(b4, vBase + ((kb * 16 + (lane & 15)) * 72 + np * 16 + (lane >> 4) * 8) * 2);
                    mma16816(accO[2 * np],     pf, b4);
                    mma16816(accO[2 * np + 1], pf, b4 + 2);
                }
            }
        }

        __syncthreads();
        if (jt < 7){
            loadKV(j0 + 128);
            asm volatile("cp.async.commit_group;");
            asm volatile("cp.async.wait_group 0;");
            __syncthreads();
        }
    }

    lsumA += __shfl_xor_sync(0xffffffffu, lsumA, 1);
    lsumA += __shfl_xor_sync(0xffffffffu, lsumA, 2);
    lsumB += __shfl_xor_sync(0xffffffffu, lsumB, 1);
    lsumB += __shfl_xor_sync(0xffffffffu, lsumB, 2);
    float invA = 1.0f / lsumA, invB = 1.0f / lsumB;
    int rA = bb * 1024 + iA, rB = bb * 1024 + iB;
    #pragma unroll
    for (int nt = 0; nt < 8; ++nt){
        int col = nn * 64 + nt * 8 + ((lane & 3) << 1);
        __nv_bfloat162 p0, p1;
        p0.x = bfc(accO[nt][0] * invA); p0.y = bfc(accO[nt][1] * invA);
        p1.x = bfc(accO[nt][2] * invB); p1.y = bfc(accO[nt][3] * invB);
        *(__nv_bfloat162*)(av16 + (long long)rA * 1024 + col) = p0;
        *(__nv_bfloat162*)(av16 + (long long)rB * 1024 + col) = p1;
    }
}

// ------------------------- merged dot kernels -------------------------
__global__ void dots_k(const bf* __restrict__ q16, const bf* __restrict__ k16,
                       const bf* __restrict__ rh16,
                       const float* __restrict__ rwb, const float* __restrict__ rrb,
                       const float* __restrict__ rsb, const float* __restrict__ seg,
                       const int* __restrict__ amask,
                       float* __restrict__ rwkm, float* __restrict__ rrt, float* __restrict__ ttd)
{
    int gw = (blockIdx.x * blockDim.x + threadIdx.x) >> 5;
    int lane = threadIdx.x & 31;
    if (blockIdx.y == 0){
        int zz = gw >> 10, j = gw & (Sc - 1);
        int b = zz >> 4, n = zz & 15;
        const bf* kp = k16 + ((long long)(b * 1024 + j)) * 1024 + n * 64;
        __nv_bfloat162 kk = ((const __nv_bfloat162*)kp)[lane];
        float2 rw = *(const float2*)(rwb + n * Hc + 2 * lane);
        float d = rw.x * __bfloat162float(kk.x) + rw.y * __bfloat162float(kk.y);
        #pragma unroll
        for (int o = 16; o; o >>= 1) d += __shfl_down_sync(0xffffffffu, d, o);
        if (lane == 0)
            rwkm[gw] = d * SCALE - INFV * (1.0f - (float)amask[b * Sc + j]);
    } else if (blockIdx.y == 1){
        int n = gw >> 11, tt2 = gw & (Rc - 1);
        const bf* rp = rh16 + (long long)tt2 * 1024 + n * 64;
        __nv_bfloat162 rr = ((const __nv_bfloat162*)rp)[lane];
        float2 rb = *(const float2*)(rrb + n * Hc + 2 * lane);
        float d = rb.x * __bfloat162float(rr.x) + rb.y * __bfloat162float(rr.y);
        #pragma unroll
        for (int o = 16; o; o >>= 1) d += __shfl_down_sync(0xffffffffu, d, o);
        if (lane == 0) rrt[gw] = d * SCALE;
    } else {
        int n = gw & 15;
        long long bi = gw >> 4;
        const bf* qp = q16 + bi * 1024 + n * 64;
        __nv_bfloat162 qq = ((const __nv_bfloat162*)qp)[lane];
        float2 e0v = *(const float2*)(seg + n * Hc + 2 * lane);
        float2 e1v = *(const float2*)(seg + Nc * Hc + n * Hc + 2 * lane);
        float2 rv  = *(const float2*)(rsb + n * Hc + 2 * lane);
        float qx = __bfloat162float(qq.x), qy = __bfloat162float(qq.y);
        float d0 = qx * e0v.x + qy * e0v.y;
        float d1 = qx * e1v.x + qy * e1v.y;
        float s0 = rv.x * e0v.x + rv.y * e0v.y;
        float s1 = rv.x * e1v.x + rv.y * e1v.y;
        #pragma unroll
        for (int o = 16; o; o >>= 1){
            d0 += __shfl_down_sync(0xffffffffu, d0, o);
            d1 += __shfl_down_sync(0xffffffffu, d1, o);
            s0 += __shfl_down_sync(0xffffffffu, s0, o);
            s1 += __shfl_down_sync(0xffffffffu, s1, o);
        }
        if (lane == 0){
            ttd[2 * gw]     = d0 + SCALE * s0;
            ttd[2 * gw + 1] = d1 + SCALE * s1;
        }
    }
}

// ------------------------- residual + LayerNorm (shuffle reduce) ---------------
__global__ void ln_k(const float* __restrict__ query, const float* __restrict__ ao,
                     const float* __restrict__ gamma, const float* __restrict__ beta,
                     float* __restrict__ out){
    __shared__ float red[16];
    long long base = (long long)blockIdx.x * Dc;
    int t = threadIdx.x, lane = t & 31, w = t >> 5;
    float x[4]; float s = 0.f, s2 = 0.f;
    #pragma unroll
    for (int u = 0; u < 4; ++u){
        x[u] = query[base + t + u * 256] + ao[base + t + u * 256];
        s += x[u]; s2 += x[u] * x[u];
    }
    #pragma unroll
    for (int o = 16; o; o >>= 1){
        s  += __shfl_xor_sync(0xffffffffu, s,  o);
        s2 += __shfl_xor_sync(0xffffffffu, s2, o);
    }
    if (lane == 0){ red[w] = s; red[8 + w] = s2; }
    __syncthreads();
    float ts = 0.f, ts2 = 0.f;
    #pragma unroll
    for (int u = 0; u < 8; ++u){ ts += red[u]; ts2 += red[8 + u]; }
    float mu = ts * (1.0f / Dc);
    float var = ts2 * (1.0f / Dc) - mu * mu;
    float inv = rsqrtf(var + EPSV);
    #pragma unroll
    for (int u = 0; u < 4; ++u){
        int c = t + u * 256;
        out[base + c] = (x[u] - mu) * inv * gamma[c] + beta[c];
    }
}

// ------------------------- driver -------------------------
extern "C" void kernel_launch(void* const* d_in, const int* in_sizes, int n_in,
                              void* d_out, int out_size)
{
    const float* query = (const float*)d_in[0];
    const float* key   = (const float*)d_in[1];
    const float* value = (const float*)d_in[2];
    const float* r     = (const float*)d_in[3];
    const float* clsm  = (const float*)d_in[4];
    const float* Wq    = (const float*)d_in[5];
    const float* Wk    = (const float*)d_in[6];
    const float* bk    = (const float*)d_in[7];
    const float* Wv    = (const float*)d_in[8];
    const float* bv    = (const float*)d_in[9];
    const float* Wo    = (const float*)d_in[10];
    const float* bo    = (const float*)d_in[11];
    const float* rwb   = (const float*)d_in[12];
    const float* rrb   = (const float*)d_in[13];
    const float* rkern = (const float*)d_in[14];
    const float* rsb   = (const float*)d_in[15];
    const float* seg   = (const float*)d_in[16];
    const float* gamma = (const float*)d_in[17];
    const float* beta  = (const float*)d_in[18];
    const unsigned char* ttm = (const unsigned char*)d_in[19];
    const int*   amask = (const int*)d_in[20];
    float* out = (float*)d_out;

    bf *in16, *w16, *proj, *av16;
    float *ao, *rwk, *rrt, *ttd;
    unsigned char* comb;
    cudaGetSymbolAddress((void**)&in16, g_in16);
    cudaGetSymbolAddress((void**)&w16,  g_w16);
    cudaGetSymbolAddress((void**)&proj, g_proj);
    cudaGetSymbolAddress((void**)&av16, g_av16);
    cudaGetSymbolAddress((void**)&ao,   g_ao);
    cudaGetSymbolAddress((void**)&rwk,  g_rwk);
    cudaGetSymbolAddress((void**)&rrt,  g_rrt);
    cudaGetSymbolAddress((void**)&ttd,  g_ttd);
    cudaGetSymbolAddress((void**)&comb, g_comb);

    bf* q16  = proj;
    bf* k16  = proj + 1LL * 2048 * 1024;
    bf* v16  = proj + 2LL * 2048 * 1024;
    bf* rh16 = proj + 3LL * 2048 * 1024;

    auto k6 = tg<128, 4, 6>;
    auto k4 = tg<128, 4, 4>;
    cudaFuncSetAttribute(k6, cudaFuncAttributeMaxDynamicSharedMemorySize, 75776);
    cudaFuncSetAttribute(k4, cudaFuncAttributeMaxDynamicSharedMemorySize, 75776);
    cudaFuncSetAttribute(fattn_k, cudaFuncAttributeMaxDynamicSharedMemorySize, 108544);

    // 0) casts + comb (merged, MLP=8)
    castAll_k<<<dim3(256, 10), 256>>>(query, key, value, r, Wq, Wk, Wv, rkern, Wo,
                                      ttm, clsm, in16, w16, comb);

    // 1) merged projections
    k6<<<dim3(8, 16, 4), 256, 75776>>>(in16, w16, bk, bv, nullptr, proj,
        1024, 1024, 1024, 0);

    // 2) merged bias-dot tables
    dots_k<<<dim3(4096, 3), 256>>>(q16, k16, rh16, rwb, rrb, rsb, seg, amask, rwk, rrt, ttd);

    // 3) fused scores + softmax + PV (2 CTAs/SM)
    fattn_k<<<dim3(8, 32), 256, 108544>>>(q16, k16, v16, rh16,
        rwk, rrt, ttd, comb, av16);

    // 4) output projection + bias
    k4<<<dim3(8, 16, 1), 256, 75776>>>(av16, w16 + 4LL * 1024 * 1024, bo, nullptr, ao, nullptr,
        1024, 1024, 1024, 1024);

    // 5) residual + LayerNorm
    ln_k<<<Bc * Sc, 256>>>(query, ao, gamma, beta, out);

    (void)in_sizes; (void)n_in; (void)out_size;
}